// round 11
// baseline (speedup 1.0000x reference)
#include <cuda_runtime.h>
#include <cuda_bf16.h>
#include <math.h>
#include <stdint.h>

// Problem constants
#define BATCH 8
#define NPTS  8192
#define SPTS  2048
#define C1V   128
#define C2V   256
#define MROWS 65536
#define K1V   384
#define N1V   256
#define K2V   256
#define N2V   128
#define RPARTS 512            // one partial per 128-row GEMM tile

// Scratch (device globals: allocation-free)
__device__ uint32_t g_Xh[(size_t)MROWS * (K1V/2)];   // X hi (packed bf16x2)
__device__ uint32_t g_Xl[(size_t)MROWS * (K1V/2)];   // X lo (residual)
__device__ uint32_t g_W1h[N1V * (K1V/2)], g_W1l[N1V * (K1V/2)];
__device__ uint32_t g_W2h[N2V * (K2V/2)], g_W2l[N2V * (K2V/2)];
__device__ float g_Y1[(size_t)MROWS * N1V];
__device__ float g_Y2[(size_t)MROWS * N2V];
__device__ int   g_idx[MROWS * 3];
__device__ float g_wt [MROWS * 3];
__device__ float g_ps1[N1V * RPARTS], g_pq1[N1V * RPARTS];   // [col][rowtile]
__device__ float g_ps2[N2V * RPARTS], g_pq2[N2V * RPARTS];
__device__ float g_sc1[N1V], g_sh1[N1V];
__device__ float g_sc2[N2V], g_sh2[N2V];

// ---------------------------------------------------------------------------
// bf16 / mma helpers
// ---------------------------------------------------------------------------
__device__ __forceinline__ uint32_t smem_u32(const void* p) {
    uint32_t a;
    asm("{ .reg .u64 t; cvta.to.shared.u64 t, %1; cvt.u32.u64 %0, t; }"
        : "=r"(a) : "l"(p));
    return a;
}
__device__ __forceinline__ void split_pack_bf16(float e, float o,
                                                uint32_t& h, uint32_t& l) {
    __nv_bfloat16 he = __float2bfloat16_rn(e);
    __nv_bfloat16 ho = __float2bfloat16_rn(o);
    float re = e - __bfloat162float(he);
    float ro = o - __bfloat162float(ho);
    __nv_bfloat162 hp = __halves2bfloat162(he, ho);
    __nv_bfloat162 lp = __floats2bfloat162_rn(re, ro);
    h = *(uint32_t*)&hp;
    l = *(uint32_t*)&lp;
}
__device__ __forceinline__ void mma16(float* c, const uint32_t* a,
                                      uint32_t b0, uint32_t b1) {
    asm volatile(
        "mma.sync.aligned.m16n8k16.row.col.f32.bf16.bf16.f32 "
        "{%0,%1,%2,%3}, {%4,%5,%6,%7}, {%8,%9}, {%0,%1,%2,%3};"
        : "+f"(c[0]), "+f"(c[1]), "+f"(c[2]), "+f"(c[3])
        : "r"(a[0]), "r"(a[1]), "r"(a[2]), "r"(a[3]), "r"(b0), "r"(b1));
}
__device__ __forceinline__ void ldsm_x4(uint32_t* r, uint32_t addr) {
    asm volatile(
        "ldmatrix.sync.aligned.m8n8.x4.shared.b16 {%0,%1,%2,%3}, [%4];"
        : "=r"(r[0]), "=r"(r[1]), "=r"(r[2]), "=r"(r[3]) : "r"(addr));
}

// ---------------------------------------------------------------------------
// Kernel 0: pre-split a weight matrix into bf16 hi/lo packed words.
// Layout matches [row][K/2 words] row-major (float4 i -> uint2 i).
// ---------------------------------------------------------------------------
__global__ void presplit_w(const float* __restrict__ w,
                           uint32_t* __restrict__ wh,
                           uint32_t* __restrict__ wl, int n4)
{
    int i = blockIdx.x * 256 + threadIdx.x;
    if (i >= n4) return;
    float4 v = ((const float4*)w)[i];
    uint32_t h0, l0, h1, l1;
    split_pack_bf16(v.x, v.y, h0, l0);
    split_pack_bf16(v.z, v.w, h1, l1);
    ((uint2*)wh)[i] = make_uint2(h0, h1);
    ((uint2*)wl)[i] = make_uint2(l0, l1);
}

// ---------------------------------------------------------------------------
// Kernel 1: 3-NN + interpolation weights (3-FMA inner loop)
// ---------------------------------------------------------------------------
__global__ void nn3_kernel(const float* __restrict__ xyz1,
                           const float* __restrict__ xyz2)
{
    __shared__ float4 s2[SPTS];
    const int b = blockIdx.y;
    const float* x2 = xyz2 + (size_t)b * SPTS * 3;
    for (int i = threadIdx.x; i < SPTS; i += blockDim.x) {
        float x = x2[i*3+0], y = x2[i*3+1], z = x2[i*3+2];
        s2[i] = make_float4(x, y, z, 0.5f*(x*x + y*y + z*z));
    }
    __syncthreads();

    const int n = blockIdx.x * blockDim.x + threadIdx.x;
    const int p = b * NPTS + n;
    const float ax = xyz1[(size_t)p*3+0];
    const float ay = xyz1[(size_t)p*3+1];
    const float az = xyz1[(size_t)p*3+2];
    const float an = ax*ax + ay*ay + az*az;

    float e0 = 1e30f, e1 = 1e30f, e2 = 1e30f;
    int   j0 = 0,     j1 = 0,     j2 = 0;
    #pragma unroll 8
    for (int s = 0; s < SPTS; s++) {
        float4 q = s2[s];
        float ee = fmaf(-ax, q.x, fmaf(-ay, q.y, fmaf(-az, q.z, q.w)));
        if (ee < e2) {
            if (ee < e1) {
                if (ee < e0) { e2=e1; j2=j1; e1=e0; j1=j0; e0=ee; j0=s; }
                else         { e2=e1; j2=j1; e1=ee; j1=s; }
            } else           { e2=ee; j2=s; }
        }
    }
    float d0 = sqrtf(fmaxf(fmaf(2.0f, e0, an), 0.0f));
    float d1 = sqrtf(fmaxf(fmaf(2.0f, e1, an), 0.0f));
    float d2 = sqrtf(fmaxf(fmaf(2.0f, e2, an), 0.0f));
    float r0 = 1.0f / (d0 + 1e-8f);
    float r1 = 1.0f / (d1 + 1e-8f);
    float r2 = 1.0f / (d2 + 1e-8f);
    float inv = 1.0f / (r0 + r1 + r2);
    g_wt[p*3+0] = r0*inv; g_wt[p*3+1] = r1*inv; g_wt[p*3+2] = r2*inv;
    g_idx[p*3+0] = j0;    g_idx[p*3+1] = j1;    g_idx[p*3+2] = j2;
}

// ---------------------------------------------------------------------------
// Kernel 2: X = [points1 | interp(points2)], written PRE-SPLIT (Xh/Xl).
// Same total bytes as fp32 X; one warp per point.
// ---------------------------------------------------------------------------
__global__ void gather_concat_kernel(const float* __restrict__ points1,
                                     const float* __restrict__ points2)
{
    const int warp = threadIdx.x >> 5;
    const int lane = threadIdx.x & 31;
    const int p = blockIdx.x * 8 + warp;
    const int b = p >> 13;

    const int   i0 = g_idx[p*3+0], i1 = g_idx[p*3+1], i2 = g_idx[p*3+2];
    const float w0 = g_wt[p*3+0],  w1 = g_wt[p*3+1],  w2 = g_wt[p*3+2];

    uint32_t* Xh = g_Xh + (size_t)p * (K1V/2);
    uint32_t* Xl = g_Xl + (size_t)p * (K1V/2);

    {
        float4 v = ((const float4*)(points1 + (size_t)p * C1V))[lane];
        uint32_t h0, l0, h1, l1;
        split_pack_bf16(v.x, v.y, h0, l0);
        split_pack_bf16(v.z, v.w, h1, l1);
        *(uint2*)(Xh + lane*2) = make_uint2(h0, h1);
        *(uint2*)(Xl + lane*2) = make_uint2(l0, l1);
    }
    const float4* pa = (const float4*)(points2 + ((size_t)b*SPTS + i0) * C2V);
    const float4* pb = (const float4*)(points2 + ((size_t)b*SPTS + i1) * C2V);
    const float4* pc = (const float4*)(points2 + ((size_t)b*SPTS + i2) * C2V);
    #pragma unroll
    for (int t = 0; t < 2; t++) {
        int c = t*32 + lane;
        float4 va = pa[c], vb = pb[c], vc = pc[c];
        float4 o;
        o.x = w0*va.x + w1*vb.x + w2*vc.x;
        o.y = w0*va.y + w1*vb.y + w2*vc.y;
        o.z = w0*va.z + w1*vb.z + w2*vc.z;
        o.w = w0*va.w + w1*vb.w + w2*vc.w;
        uint32_t h0, l0, h1, l1;
        split_pack_bf16(o.x, o.y, h0, l0);
        split_pack_bf16(o.z, o.w, h1, l1);
        *(uint2*)(Xh + 64 + c*2) = make_uint2(h0, h1);
        *(uint2*)(Xl + 64 + c*2) = make_uint2(l0, l1);
    }
}

// ---------------------------------------------------------------------------
// bf16x3 m16n8k16 GEMM (R9/R10 config; pre-split operand streams).
// !TRANS_A: A pre-split (Ah/Al), zero in-loop conversions, 4 LDG.128 +
//           4 STS.128 per thread per k16 stage.
// TRANS_A : A fp32 + fused relu(a*scale+shift) + in-loop split (read-once).
// B always pre-split. LDSM fragment loads, 2 CTAs/SM, double-buffered.
// Epilogue: +bias, Y store, fused BN partials (TRANSPOSED [col][rowtile]).
// ---------------------------------------------------------------------------
#define TROW_W 12                      // uint32 words per tile row
#define TILE_WRD (128 * TROW_W)
#define BUF_WRD (4 * TILE_WRD)         // Ah|Al|Bh|Bl per buffer

template<int KDIM, bool TRANS_A>
__global__ void __launch_bounds__(256, 2)
gemm_mma(const float* __restrict__ A,        // fp32 A (TRANS_A only)
         const uint32_t* __restrict__ Ah,    // pre-split A (!TRANS_A)
         const uint32_t* __restrict__ Al,
         const uint32_t* __restrict__ Bh,    // pre-split W (always)
         const uint32_t* __restrict__ Bl,
         const float* __restrict__ bias,
         const float* __restrict__ aScale,
         const float* __restrict__ aShift,
         float* __restrict__ Y,
         float* __restrict__ psum,
         float* __restrict__ psq,
         int N)
{
    constexpr int KW = KDIM / 2;        // words per row in pre-split arrays
    extern __shared__ float sm[];
    float* sSc = sm;                    // [384]
    float* sSh = sm + 384;              // [384]
    uint32_t* tiles = (uint32_t*)(sm + 768);

    const int tid  = threadIdx.x;
    const int wid  = tid >> 5;
    const int lane = tid & 31;
    const int lg   = lane >> 2;
    const int lt   = lane & 3;
    const int wm   = (wid & 3) * 32;
    const int wn   = (wid >> 2) * 64;

    // ldmatrix per-lane addressing (bytes)
    const uint32_t tilesAddr = smem_u32(tiles);
    const int aRow = lane & 15;
    const int aOff = (lane >> 4) * 16;
    const int bRow = (lane & 7) + ((lane >> 4) << 3);
    const int bOff = ((lane >> 3) & 1) * 16;

    if (TRANS_A) {
        for (int i = tid; i < KDIM; i += 256) { sSc[i] = aScale[i]; sSh[i] = aShift[i]; }
        __syncthreads();
    }

    float acc[2][8][4];
    #pragma unroll
    for (int mt = 0; mt < 2; mt++)
        #pragma unroll
        for (int nt = 0; nt < 8; nt++)
            #pragma unroll
            for (int j = 0; j < 4; j++) acc[mt][nt][j] = 0.0f;

    // loader indices
    const int r  = tid >> 2;           // fp32 A path: row 0..63 (+64)
    const int q  = tid & 3;            //              float4 slot
    const int pr = tid >> 1;           // pre-split path: row 0..127
    const int ph = tid & 1;            //                 half-chunk 0/1

    const float*    Afb = TRANS_A ? (A + (size_t)blockIdx.y * 128 * KDIM) : nullptr;
    const uint32_t* Ahb = TRANS_A ? nullptr : (Ah + (size_t)blockIdx.y * 128 * KW);
    const uint32_t* Alb = TRANS_A ? nullptr : (Al + (size_t)blockIdx.y * 128 * KW);
    const uint32_t* Bhb = Bh + (size_t)blockIdx.x * 128 * KW;
    const uint32_t* Blb = Bl + (size_t)blockIdx.x * 128 * KW;

    float4 av[2];
    uint4  ahv, alv, bhv, blv;

    auto g_load = [&](int k0) {
        const int kw = k0 >> 1;
        if (TRANS_A) {
            #pragma unroll
            for (int i = 0; i < 2; i++) {
                int rr = i*64 + r;
                float4 v = *(const float4*)(Afb + (size_t)rr*KDIM + k0 + q*4);
                int kb = k0 + q*4;
                v.x = fmaxf(fmaf(v.x, sSc[kb+0], sSh[kb+0]), 0.0f);
                v.y = fmaxf(fmaf(v.y, sSc[kb+1], sSh[kb+1]), 0.0f);
                v.z = fmaxf(fmaf(v.z, sSc[kb+2], sSh[kb+2]), 0.0f);
                v.w = fmaxf(fmaf(v.w, sSc[kb+3], sSh[kb+3]), 0.0f);
                av[i] = v;
            }
        } else {
            ahv = *(const uint4*)(Ahb + (size_t)pr*KW + kw + ph*4);
            alv = *(const uint4*)(Alb + (size_t)pr*KW + kw + ph*4);
        }
        bhv = *(const uint4*)(Bhb + (size_t)pr*KW + kw + ph*4);
        blv = *(const uint4*)(Blb + (size_t)pr*KW + kw + ph*4);
    };
    auto s_store = [&](int buf) {
        uint32_t* base = tiles + buf * BUF_WRD;
        if (TRANS_A) {
            #pragma unroll
            for (int i = 0; i < 2; i++) {
                const int rr = i*64 + r;
                const int wo = rr * TROW_W + q*2;
                uint32_t h0, l0, h1, l1;
                split_pack_bf16(av[i].x, av[i].y, h0, l0);
                split_pack_bf16(av[i].z, av[i].w, h1, l1);
                *(uint2*)(base + wo)            = make_uint2(h0, h1);
                *(uint2*)(base + TILE_WRD + wo) = make_uint2(l0, l1);
            }
        } else {
            const int wo = pr * TROW_W + ph*4;
            *(uint4*)(base + wo)            = ahv;
            *(uint4*)(base + TILE_WRD + wo) = alv;
        }
        const int wo = pr * TROW_W + ph*4;
        *(uint4*)(base + 2*TILE_WRD + wo) = bhv;
        *(uint4*)(base + 3*TILE_WRD + wo) = blv;
    };
    auto do_mma = [&](int buf) {
        const uint32_t tb = tilesAddr + buf * (BUF_WRD * 4);
        uint32_t ahr[2][4], alr[2][4];
        #pragma unroll
        for (int mt = 0; mt < 2; mt++) {
            const uint32_t ad = tb + (uint32_t)((wm + mt*16 + aRow) * TROW_W) * 4 + aOff;
            ldsm_x4(ahr[mt], ad);
            ldsm_x4(alr[mt], ad + TILE_WRD * 4);
        }
        #pragma unroll
        for (int ntp = 0; ntp < 4; ntp++) {
            const uint32_t bd = tb + 2*TILE_WRD*4
                + (uint32_t)((wn + ntp*16 + bRow) * TROW_W) * 4 + bOff;
            uint32_t bh[4], bl[4];
            ldsm_x4(bh, bd);
            ldsm_x4(bl, bd + TILE_WRD * 4);
            #pragma unroll
            for (int s = 0; s < 2; s++) {
                const int nt = ntp*2 + s;
                #pragma unroll
                for (int mt = 0; mt < 2; mt++) {
                    mma16(acc[mt][nt], ahr[mt], bh[2*s], bh[2*s+1]);
                    mma16(acc[mt][nt], alr[mt], bh[2*s], bh[2*s+1]);
                    mma16(acc[mt][nt], ahr[mt], bl[2*s], bl[2*s+1]);
                }
            }
        }
    };

    const int KT = KDIM / 16;
    g_load(0);
    s_store(0);
    __syncthreads();
    for (int kt = 0; kt < KT; kt++) {
        if (kt + 1 < KT) g_load((kt + 1) * 16);
        do_mma(kt & 1);
        if (kt + 1 < KT) {
            s_store((kt + 1) & 1);
            __syncthreads();
        }
    }

    // ---- Epilogue: +bias, store Y, fused BN partial stats
    #pragma unroll
    for (int nt = 0; nt < 8; nt++) {
        const int col = blockIdx.x*128 + wn + nt*8 + 2*lt;
        const float b0 = __ldg(&bias[col]), b1 = __ldg(&bias[col+1]);
        #pragma unroll
        for (int mt = 0; mt < 2; mt++) {
            acc[mt][nt][0] += b0; acc[mt][nt][1] += b1;
            acc[mt][nt][2] += b0; acc[mt][nt][3] += b1;
            const int row0 = blockIdx.y*128 + wm + mt*16 + lg;
            *(float2*)(Y + (size_t)row0 * N + col) =
                make_float2(acc[mt][nt][0], acc[mt][nt][1]);
            *(float2*)(Y + (size_t)(row0+8) * N + col) =
                make_float2(acc[mt][nt][2], acc[mt][nt][3]);
        }
    }

    __syncthreads();                      // reuse tiles as reduction space
    float* srs = (float*)tiles;
    float* srq = (float*)tiles + 512;
    #pragma unroll
    for (int nt = 0; nt < 8; nt++) {
        float sA = acc[0][nt][0] + acc[0][nt][2] + acc[1][nt][0] + acc[1][nt][2];
        float sB = acc[0][nt][1] + acc[0][nt][3] + acc[1][nt][1] + acc[1][nt][3];
        float qA = acc[0][nt][0]*acc[0][nt][0] + acc[0][nt][2]*acc[0][nt][2]
                 + acc[1][nt][0]*acc[1][nt][0] + acc[1][nt][2]*acc[1][nt][2];
        float qB = acc[0][nt][1]*acc[0][nt][1] + acc[0][nt][3]*acc[0][nt][3]
                 + acc[1][nt][1]*acc[1][nt][1] + acc[1][nt][3]*acc[1][nt][3];
        #pragma unroll
        for (int o = 4; o <= 16; o <<= 1) {
            sA += __shfl_xor_sync(0xFFFFFFFFu, sA, o);
            sB += __shfl_xor_sync(0xFFFFFFFFu, sB, o);
            qA += __shfl_xor_sync(0xFFFFFFFFu, qA, o);
            qB += __shfl_xor_sync(0xFFFFFFFFu, qB, o);
        }
        if (lane < 4) {
            srs[wid*64 + nt*8 + lane*2 + 0] = sA;
            srs[wid*64 + nt*8 + lane*2 + 1] = sB;
            srq[wid*64 + nt*8 + lane*2 + 0] = qA;
            srq[wid*64 + nt*8 + lane*2 + 1] = qB;
        }
    }
    __syncthreads();
    if (tid < 128) {
        const int w0 = tid >> 6, cc = tid & 63;
        float s = 0.0f, qq = 0.0f;
        #pragma unroll
        for (int k = 0; k < 4; k++) {
            s  += srs[(w0*4 + k)*64 + cc];
            qq += srq[(w0*4 + k)*64 + cc];
        }
        const size_t o = (size_t)(blockIdx.x*128 + tid) * RPARTS + blockIdx.y;
        psum[o] = s;
        psq [o] = qq;
    }
}

// ---------------------------------------------------------------------------
// BN stats stage 2: one block per channel; 512 contiguous partials.
// ---------------------------------------------------------------------------
__global__ void bn_stats2(const float* __restrict__ ps, const float* __restrict__ pq,
                          const float* __restrict__ g,
                          const float* __restrict__ beta,
                          float* __restrict__ scale, float* __restrict__ shift)
{
    __shared__ float ss[4], sq[4];
    const int c = blockIdx.x, tid = threadIdx.x;   // 128 threads
    float4 v = ((const float4*)(ps + (size_t)c * RPARTS))[tid];
    float4 w = ((const float4*)(pq + (size_t)c * RPARTS))[tid];
    float s = (v.x + v.y) + (v.z + v.w);
    float q = (w.x + w.y) + (w.z + w.w);
    #pragma unroll
    for (int o = 16; o >= 1; o >>= 1) {
        s += __shfl_down_sync(0xFFFFFFFFu, s, o);
        q += __shfl_down_sync(0xFFFFFFFFu, q, o);
    }
    if ((tid & 31) == 0) { ss[tid >> 5] = s; sq[tid >> 5] = q; }
    __syncthreads();
    if (tid == 0) {
        double S = ((double)ss[0] + (double)ss[1]) + ((double)ss[2] + (double)ss[3]);
        double Q = ((double)sq[0] + (double)sq[1]) + ((double)sq[2] + (double)sq[3]);
        double mu  = S / (double)MROWS;
        double var = Q / (double)MROWS - mu * mu;
        float sc = g[c] / sqrtf((float)var + 1e-5f);
        scale[c] = sc;
        shift[c] = beta[c] - (float)mu * sc;
    }
}

// ---------------------------------------------------------------------------
// Final: out = relu(Y2 * scale2 + shift2)
// ---------------------------------------------------------------------------
__global__ void bn_relu_out_kernel(const float* __restrict__ Y,
                                   float* __restrict__ out)
{
    int i = blockIdx.x * blockDim.x + threadIdx.x;
    const float4 v = ((const float4*)Y)[i];
    int c = (i * 4) & (N2V - 1);
    float4 o;
    o.x = fmaxf(fmaf(v.x, g_sc2[c+0], g_sh2[c+0]), 0.0f);
    o.y = fmaxf(fmaf(v.y, g_sc2[c+1], g_sh2[c+1]), 0.0f);
    o.z = fmaxf(fmaf(v.z, g_sc2[c+2], g_sh2[c+2]), 0.0f);
    o.w = fmaxf(fmaf(v.w, g_sc2[c+3], g_sh2[c+3]), 0.0f);
    ((float4*)out)[i] = o;
}

// ---------------------------------------------------------------------------
// Launcher (graph-capturable)
// ---------------------------------------------------------------------------
extern "C" void kernel_launch(void* const* d_in, const int* in_sizes, int n_in,
                              void* d_out, int out_size)
{
    const float* xyz1    = (const float*)d_in[0];
    const float* xyz2    = (const float*)d_in[1];
    const float* points1 = (const float*)d_in[2];
    const float* points2 = (const float*)d_in[3];
    const float* w1      = (const float*)d_in[4];
    const float* b1      = (const float*)d_in[5];
    const float* g1      = (const float*)d_in[6];
    const float* beta1   = (const float*)d_in[7];
    const float* w2      = (const float*)d_in[8];
    const float* b2      = (const float*)d_in[9];
    const float* g2      = (const float*)d_in[10];
    const float* beta2   = (const float*)d_in[11];
    float* out = (float*)d_out;

    uint32_t *pXh, *pXl, *pW1h, *pW1l, *pW2h, *pW2l;
    float *pY1, *pY2, *pps1, *ppq1, *pps2, *ppq2, *psc1, *psh1, *psc2, *psh2;
    cudaGetSymbolAddress((void**)&pXh,  g_Xh);
    cudaGetSymbolAddress((void**)&pXl,  g_Xl);
    cudaGetSymbolAddress((void**)&pW1h, g_W1h);
    cudaGetSymbolAddress((void**)&pW1l, g_W1l);
    cudaGetSymbolAddress((void**)&pW2h, g_W2h);
    cudaGetSymbolAddress((void**)&pW2l, g_W2l);
    cudaGetSymbolAddress((void**)&pY1,  g_Y1);
    cudaGetSymbolAddress((void**)&pY2,  g_Y2);
    cudaGetSymbolAddress((void**)&pps1, g_ps1);
    cudaGetSymbolAddress((void**)&ppq1, g_pq1);
    cudaGetSymbolAddress((void**)&pps2, g_ps2);
    cudaGetSymbolAddress((void**)&ppq2, g_pq2);
    cudaGetSymbolAddress((void**)&psc1, g_sc1);
    cudaGetSymbolAddress((void**)&psh1, g_sh1);
    cudaGetSymbolAddress((void**)&psc2, g_sc2);
    cudaGetSymbolAddress((void**)&psh2, g_sh2);

    const int SMEM = 768*4 + 2 * BUF_WRD * 4;    // 52224 B
    cudaFuncSetAttribute(gemm_mma<K1V, false>,
                         cudaFuncAttributeMaxDynamicSharedMemorySize, SMEM);
    cudaFuncSetAttribute(gemm_mma<K2V, true>,
                         cudaFuncAttributeMaxDynamicSharedMemorySize, SMEM);

    presplit_w<<<(N1V*K1V/4 + 255)/256, 256>>>(w1, pW1h, pW1l, N1V*K1V/4);
    presplit_w<<<(N2V*K2V/4 + 255)/256, 256>>>(w2, pW2h, pW2l, N2V*K2V/4);

    nn3_kernel<<<dim3(NPTS/256, BATCH), 256>>>(xyz1, xyz2);
    gather_concat_kernel<<<MROWS/8, 256>>>(points1, points2);

    gemm_mma<K1V, false><<<dim3(N1V/128, MROWS/128), 256, SMEM>>>(
        nullptr, pXh, pXl, pW1h, pW1l, b1, nullptr, nullptr,
        pY1, pps1, ppq1, N1V);
    bn_stats2<<<N1V, 128>>>(pps1, ppq1, g1, beta1, psc1, psh1);

    gemm_mma<K2V, true><<<dim3(N2V/128, MROWS/128), 256, SMEM>>>(
        pY1, nullptr, nullptr, pW2h, pW2l, b2, psc1, psh1,
        pY2, pps2, ppq2, N2V);
    bn_stats2<<<N2V, 128>>>(pps2, ppq2, g2, beta2, psc2, psh2);

    bn_relu_out_kernel<<<(MROWS * N2V / 4) / 256, 256>>>(pY2, out);
}

// round 12
// speedup vs baseline: 1.0328x; 1.0328x over previous
#include <cuda_runtime.h>
#include <cuda_bf16.h>
#include <math.h>
#include <stdint.h>

// Problem constants
#define BATCH 8
#define NPTS  8192
#define SPTS  2048
#define C1V   128
#define C2V   256
#define MROWS 65536
#define K1V   384
#define N1V   256
#define K2V   256
#define N2V   128
#define RPARTS 512            // one partial per 128-row GEMM tile

// Scratch (device globals: allocation-free)
__device__ float g_X [(size_t)MROWS * K1V];
__device__ float g_Y1[(size_t)MROWS * N1V];
__device__ float g_Y2[(size_t)MROWS * N2V];
__device__ int   g_idx[MROWS * 3];
__device__ float g_wt [MROWS * 3];
__device__ float g_ps1[N1V * RPARTS], g_pq1[N1V * RPARTS];   // [col][rowtile]
__device__ float g_ps2[N2V * RPARTS], g_pq2[N2V * RPARTS];
__device__ float g_sc1[N1V], g_sh1[N1V];
__device__ float g_sc2[N2V], g_sh2[N2V];

// ---------------------------------------------------------------------------
// bf16 / mma helpers
// ---------------------------------------------------------------------------
__device__ __forceinline__ uint32_t smem_u32(const void* p) {
    uint32_t a;
    asm("{ .reg .u64 t; cvta.to.shared.u64 t, %1; cvt.u32.u64 %0, t; }"
        : "=r"(a) : "l"(p));
    return a;
}
__device__ __forceinline__ void split_pack_bf16(float e, float o,
                                                uint32_t& h, uint32_t& l) {
    __nv_bfloat16 he = __float2bfloat16_rn(e);
    __nv_bfloat16 ho = __float2bfloat16_rn(o);
    float re = e - __bfloat162float(he);
    float ro = o - __bfloat162float(ho);
    __nv_bfloat162 hp = __halves2bfloat162(he, ho);
    __nv_bfloat162 lp = __floats2bfloat162_rn(re, ro);
    h = *(uint32_t*)&hp;
    l = *(uint32_t*)&lp;
}
__device__ __forceinline__ void mma16(float* c, const uint32_t* a,
                                      uint32_t b0, uint32_t b1) {
    asm volatile(
        "mma.sync.aligned.m16n8k16.row.col.f32.bf16.bf16.f32 "
        "{%0,%1,%2,%3}, {%4,%5,%6,%7}, {%8,%9}, {%0,%1,%2,%3};"
        : "+f"(c[0]), "+f"(c[1]), "+f"(c[2]), "+f"(c[3])
        : "r"(a[0]), "r"(a[1]), "r"(a[2]), "r"(a[3]), "r"(b0), "r"(b1));
}
__device__ __forceinline__ void ldsm_x4(uint32_t* r, uint32_t addr) {
    asm volatile(
        "ldmatrix.sync.aligned.m8n8.x4.shared.b16 {%0,%1,%2,%3}, [%4];"
        : "=r"(r[0]), "=r"(r[1]), "=r"(r[2]), "=r"(r[3]) : "r"(addr));
}

// ---------------------------------------------------------------------------
// Kernel 1: 3-NN + interpolation weights (3-FMA inner loop)
// ---------------------------------------------------------------------------
__global__ void nn3_kernel(const float* __restrict__ xyz1,
                           const float* __restrict__ xyz2)
{
    __shared__ float4 s2[SPTS];
    const int b = blockIdx.y;
    const float* x2 = xyz2 + (size_t)b * SPTS * 3;
    for (int i = threadIdx.x; i < SPTS; i += blockDim.x) {
        float x = x2[i*3+0], y = x2[i*3+1], z = x2[i*3+2];
        s2[i] = make_float4(x, y, z, 0.5f*(x*x + y*y + z*z));
    }
    __syncthreads();

    const int n = blockIdx.x * blockDim.x + threadIdx.x;
    const int p = b * NPTS + n;
    const float ax = xyz1[(size_t)p*3+0];
    const float ay = xyz1[(size_t)p*3+1];
    const float az = xyz1[(size_t)p*3+2];
    const float an = ax*ax + ay*ay + az*az;

    float e0 = 1e30f, e1 = 1e30f, e2 = 1e30f;
    int   j0 = 0,     j1 = 0,     j2 = 0;
    #pragma unroll 8
    for (int s = 0; s < SPTS; s++) {
        float4 q = s2[s];
        float ee = fmaf(-ax, q.x, fmaf(-ay, q.y, fmaf(-az, q.z, q.w)));
        if (ee < e2) {
            if (ee < e1) {
                if (ee < e0) { e2=e1; j2=j1; e1=e0; j1=j0; e0=ee; j0=s; }
                else         { e2=e1; j2=j1; e1=ee; j1=s; }
            } else           { e2=ee; j2=s; }
        }
    }
    float d0 = sqrtf(fmaxf(fmaf(2.0f, e0, an), 0.0f));
    float d1 = sqrtf(fmaxf(fmaf(2.0f, e1, an), 0.0f));
    float d2 = sqrtf(fmaxf(fmaf(2.0f, e2, an), 0.0f));
    float r0 = 1.0f / (d0 + 1e-8f);
    float r1 = 1.0f / (d1 + 1e-8f);
    float r2 = 1.0f / (d2 + 1e-8f);
    float inv = 1.0f / (r0 + r1 + r2);
    g_wt[p*3+0] = r0*inv; g_wt[p*3+1] = r1*inv; g_wt[p*3+2] = r2*inv;
    g_idx[p*3+0] = j0;    g_idx[p*3+1] = j1;    g_idx[p*3+2] = j2;
}

// ---------------------------------------------------------------------------
// Kernel 2: X = [points1 | interp(points2)]  ([MROWS, 384], fp32)
// ---------------------------------------------------------------------------
__global__ void gather_concat_kernel(const float* __restrict__ points1,
                                     const float* __restrict__ points2)
{
    const int warp = threadIdx.x >> 5;
    const int lane = threadIdx.x & 31;
    const int p = blockIdx.x * 8 + warp;
    const int b = p >> 13;

    const int   i0 = g_idx[p*3+0], i1 = g_idx[p*3+1], i2 = g_idx[p*3+2];
    const float w0 = g_wt[p*3+0],  w1 = g_wt[p*3+1],  w2 = g_wt[p*3+2];

    const float4* p1 = (const float4*)(points1 + (size_t)p * C1V);
    float4* Xr = (float4*)(g_X + (size_t)p * K1V);
    Xr[lane] = p1[lane];

    const float4* pa = (const float4*)(points2 + ((size_t)b*SPTS + i0) * C2V);
    const float4* pb = (const float4*)(points2 + ((size_t)b*SPTS + i1) * C2V);
    const float4* pc = (const float4*)(points2 + ((size_t)b*SPTS + i2) * C2V);
    #pragma unroll
    for (int t = 0; t < 2; t++) {
        int c = t*32 + lane;
        float4 va = pa[c], vb = pb[c], vc = pc[c];
        float4 o;
        o.x = w0*va.x + w1*vb.x + w2*vc.x;
        o.y = w0*va.y + w1*vb.y + w2*vc.y;
        o.z = w0*va.z + w1*vb.z + w2*vc.z;
        o.w = w0*va.w + w1*vb.w + w2*vc.w;
        Xr[32 + c] = o;
    }
}

// ---------------------------------------------------------------------------
// bf16x3 m16n8k16 GEMM (R9 data path + TERM-MAJOR MMA scheduling).
// CTA 128x128, BK=16, 8 warps (4m x 2n), warp tile 32x64, double-buffered,
// 2 CTAs/SM, LDSM fragment loads.
// KEY CHANGE vs R9/R10: the 3 split-term HMMAs for one accumulator were
// issued back-to-back (asm volatile -> ptxas cannot reorder; in-order issue
// stalls the warp ~HMMA-latency per term). Now each half (4 n-tiles) runs
// three term-major passes (hh over 8 tiles, then lh, then hl) so same-acc
// HMMAs are 8 independent HMMAs apart.
// Epilogue: +bias, Y store, fused BN partials (TRANSPOSED [col][rowtile]).
// TRANS_A fuses relu(a*scale+shift) (previous BN) into the A global load.
// ---------------------------------------------------------------------------
#define TROW_W 12                      // uint32 words per tile row
#define TILE_WRD (128 * TROW_W)
#define BUF_WRD (4 * TILE_WRD)         // Ah|Al|Bh|Bl per buffer

template<int KDIM, bool TRANS_A>
__global__ void __launch_bounds__(256, 2)
gemm_mma(const float* __restrict__ A,
         const float* __restrict__ W,
         const float* __restrict__ bias,
         const float* __restrict__ aScale,
         const float* __restrict__ aShift,
         float* __restrict__ Y,
         float* __restrict__ psum,
         float* __restrict__ psq,
         int N)
{
    extern __shared__ float sm[];
    float* sSc = sm;                    // [384]
    float* sSh = sm + 384;              // [384]
    uint32_t* tiles = (uint32_t*)(sm + 768);

    const int tid  = threadIdx.x;
    const int wid  = tid >> 5;
    const int lane = tid & 31;
    const int lg   = lane >> 2;
    const int lt   = lane & 3;
    const int wm   = (wid & 3) * 32;
    const int wn   = (wid >> 2) * 64;

    // ldmatrix per-lane addressing (bytes)
    const uint32_t tilesAddr = smem_u32(tiles);
    const int aRow = lane & 15;
    const int aOff = (lane >> 4) * 16;
    const int bRow = (lane & 7) + ((lane >> 4) << 3);
    const int bOff = ((lane >> 3) & 1) * 16;

    if (TRANS_A) {
        for (int i = tid; i < KDIM; i += 256) { sSc[i] = aScale[i]; sSh[i] = aShift[i]; }
        __syncthreads();
    }

    float acc[2][8][4];
    #pragma unroll
    for (int mt = 0; mt < 2; mt++)
        #pragma unroll
        for (int nt = 0; nt < 8; nt++)
            #pragma unroll
            for (int j = 0; j < 4; j++) acc[mt][nt][j] = 0.0f;

    const float* Ab = A + (size_t)blockIdx.y * 128 * KDIM;
    const float* Wb = W + (size_t)blockIdx.x * 128 * KDIM;

    const int r = tid >> 2;            // 0..63
    const int q = tid & 3;             // float4 slot within k16

    float4 av[2], wv[2];
    auto g_load = [&](int k0) {
        #pragma unroll
        for (int i = 0; i < 2; i++) {
            int rr = i*64 + r;
            float4 v = *(const float4*)(Ab + (size_t)rr*KDIM + k0 + q*4);
            if (TRANS_A) {
                int kb = k0 + q*4;
                v.x = fmaxf(fmaf(v.x, sSc[kb+0], sSh[kb+0]), 0.0f);
                v.y = fmaxf(fmaf(v.y, sSc[kb+1], sSh[kb+1]), 0.0f);
                v.z = fmaxf(fmaf(v.z, sSc[kb+2], sSh[kb+2]), 0.0f);
                v.w = fmaxf(fmaf(v.w, sSc[kb+3], sSh[kb+3]), 0.0f);
            }
            av[i] = v;
            wv[i] = *(const float4*)(Wb + (size_t)rr*KDIM + k0 + q*4);
        }
    };
    auto s_store = [&](int buf) {
        uint32_t* base = tiles + buf * BUF_WRD;
        #pragma unroll
        for (int i = 0; i < 2; i++) {
            const int rr = i*64 + r;
            const int wo = rr * TROW_W + q*2;
            uint32_t h0, l0, h1, l1;
            split_pack_bf16(av[i].x, av[i].y, h0, l0);
            split_pack_bf16(av[i].z, av[i].w, h1, l1);
            *(uint2*)(base + wo)              = make_uint2(h0, h1);  // Ah
            *(uint2*)(base + TILE_WRD + wo)   = make_uint2(l0, l1);  // Al
            split_pack_bf16(wv[i].x, wv[i].y, h0, l0);
            split_pack_bf16(wv[i].z, wv[i].w, h1, l1);
            *(uint2*)(base + 2*TILE_WRD + wo) = make_uint2(h0, h1);  // Bh
            *(uint2*)(base + 3*TILE_WRD + wo) = make_uint2(l0, l1);  // Bl
        }
    };
    auto do_mma = [&](int buf) {
        const uint32_t tb = tilesAddr + buf * (BUF_WRD * 4);
        uint32_t ahr[2][4], alr[2][4];
        #pragma unroll
        for (int mt = 0; mt < 2; mt++) {
            const uint32_t ad = tb + (uint32_t)((wm + mt*16 + aRow) * TROW_W) * 4 + aOff;
            ldsm_x4(ahr[mt], ad);
            ldsm_x4(alr[mt], ad + TILE_WRD * 4);
        }
        #pragma unroll
        for (int half = 0; half < 2; half++) {
            uint32_t bh[2][4], bl[2][4];
            #pragma unroll
            for (int g = 0; g < 2; g++) {
                const int ntp = half*2 + g;
                const uint32_t bd = tb + 2*TILE_WRD*4
                    + (uint32_t)((wn + ntp*16 + bRow) * TROW_W) * 4 + bOff;
                ldsm_x4(bh[g], bd);
                ldsm_x4(bl[g], bd + TILE_WRD * 4);
            }
            // pass 1: ah * bh  (8 independent HMMAs)
            #pragma unroll
            for (int g = 0; g < 2; g++)
                #pragma unroll
                for (int s = 0; s < 2; s++)
                    #pragma unroll
                    for (int mt = 0; mt < 2; mt++)
                        mma16(acc[mt][half*4 + g*2 + s], ahr[mt],
                              bh[g][2*s], bh[g][2*s+1]);
            // pass 2: al * bh
            #pragma unroll
            for (int g = 0; g < 2; g++)
                #pragma unroll
                for (int s = 0; s < 2; s++)
                    #pragma unroll
                    for (int mt = 0; mt < 2; mt++)
                        mma16(acc[mt][half*4 + g*2 + s], alr[mt],
                              bh[g][2*s], bh[g][2*s+1]);
            // pass 3: ah * bl
            #pragma unroll
            for (int g = 0; g < 2; g++)
                #pragma unroll
                for (int s = 0; s < 2; s++)
                    #pragma unroll
                    for (int mt = 0; mt < 2; mt++)
                        mma16(acc[mt][half*4 + g*2 + s], ahr[mt],
                              bl[g][2*s], bl[g][2*s+1]);
        }
    };

    const int KT = KDIM / 16;
    g_load(0);
    s_store(0);
    __syncthreads();
    for (int kt = 0; kt < KT; kt++) {
        if (kt + 1 < KT) g_load((kt + 1) * 16);
        do_mma(kt & 1);
        if (kt + 1 < KT) {
            s_store((kt + 1) & 1);
            __syncthreads();
        }
    }

    // ---- Epilogue: +bias, store Y, fused BN partial stats
    #pragma unroll
    for (int nt = 0; nt < 8; nt++) {
        const int col = blockIdx.x*128 + wn + nt*8 + 2*lt;
        const float b0 = __ldg(&bias[col]), b1 = __ldg(&bias[col+1]);
        #pragma unroll
        for (int mt = 0; mt < 2; mt++) {
            acc[mt][nt][0] += b0; acc[mt][nt][1] += b1;
            acc[mt][nt][2] += b0; acc[mt][nt][3] += b1;
            const int row0 = blockIdx.y*128 + wm + mt*16 + lg;
            *(float2*)(Y + (size_t)row0 * N + col) =
                make_float2(acc[mt][nt][0], acc[mt][nt][1]);
            *(float2*)(Y + (size_t)(row0+8) * N + col) =
                make_float2(acc[mt][nt][2], acc[mt][nt][3]);
        }
    }

    __syncthreads();                      // reuse tiles as reduction space
    float* srs = (float*)tiles;
    float* srq = (float*)tiles + 512;
    #pragma unroll
    for (int nt = 0; nt < 8; nt++) {
        float sA = acc[0][nt][0] + acc[0][nt][2] + acc[1][nt][0] + acc[1][nt][2];
        float sB = acc[0][nt][1] + acc[0][nt][3] + acc[1][nt][1] + acc[1][nt][3];
        float qA = acc[0][nt][0]*acc[0][nt][0] + acc[0][nt][2]*acc[0][nt][2]
                 + acc[1][nt][0]*acc[1][nt][0] + acc[1][nt][2]*acc[1][nt][2];
        float qB = acc[0][nt][1]*acc[0][nt][1] + acc[0][nt][3]*acc[0][nt][3]
                 + acc[1][nt][1]*acc[1][nt][1] + acc[1][nt][3]*acc[1][nt][3];
        #pragma unroll
        for (int o = 4; o <= 16; o <<= 1) {
            sA += __shfl_xor_sync(0xFFFFFFFFu, sA, o);
            sB += __shfl_xor_sync(0xFFFFFFFFu, sB, o);
            qA += __shfl_xor_sync(0xFFFFFFFFu, qA, o);
            qB += __shfl_xor_sync(0xFFFFFFFFu, qB, o);
        }
        if (lane < 4) {
            srs[wid*64 + nt*8 + lane*2 + 0] = sA;
            srs[wid*64 + nt*8 + lane*2 + 1] = sB;
            srq[wid*64 + nt*8 + lane*2 + 0] = qA;
            srq[wid*64 + nt*8 + lane*2 + 1] = qB;
        }
    }
    __syncthreads();
    if (tid < 128) {
        const int w0 = tid >> 6, cc = tid & 63;
        float s = 0.0f, qq = 0.0f;
        #pragma unroll
        for (int k = 0; k < 4; k++) {
            s  += srs[(w0*4 + k)*64 + cc];
            qq += srq[(w0*4 + k)*64 + cc];
        }
        // transposed: [col][rowtile] -> contiguous per-channel reduction
        const size_t o = (size_t)(blockIdx.x*128 + tid) * RPARTS + blockIdx.y;
        psum[o] = s;
        psq [o] = qq;
    }
}

// ---------------------------------------------------------------------------
// BN stats stage 2: one block per channel; 512 contiguous partials.
// ---------------------------------------------------------------------------
__global__ void bn_stats2(const float* __restrict__ ps, const float* __restrict__ pq,
                          const float* __restrict__ g,
                          const float* __restrict__ beta,
                          float* __restrict__ scale, float* __restrict__ shift)
{
    __shared__ float ss[4], sq[4];
    const int c = blockIdx.x, tid = threadIdx.x;   // 128 threads
    float4 v = ((const float4*)(ps + (size_t)c * RPARTS))[tid];
    float4 w = ((const float4*)(pq + (size_t)c * RPARTS))[tid];
    float s = (v.x + v.y) + (v.z + v.w);
    float q = (w.x + w.y) + (w.z + w.w);
    #pragma unroll
    for (int o = 16; o >= 1; o >>= 1) {
        s += __shfl_down_sync(0xFFFFFFFFu, s, o);
        q += __shfl_down_sync(0xFFFFFFFFu, q, o);
    }
    if ((tid & 31) == 0) { ss[tid >> 5] = s; sq[tid >> 5] = q; }
    __syncthreads();
    if (tid == 0) {
        double S = ((double)ss[0] + (double)ss[1]) + ((double)ss[2] + (double)ss[3]);
        double Q = ((double)sq[0] + (double)sq[1]) + ((double)sq[2] + (double)sq[3]);
        double mu  = S / (double)MROWS;
        double var = Q / (double)MROWS - mu * mu;
        float sc = g[c] / sqrtf((float)var + 1e-5f);
        scale[c] = sc;
        shift[c] = beta[c] - (float)mu * sc;
    }
}

// ---------------------------------------------------------------------------
// Final: out = relu(Y2 * scale2 + shift2)
// ---------------------------------------------------------------------------
__global__ void bn_relu_out_kernel(const float* __restrict__ Y,
                                   float* __restrict__ out)
{
    int i = blockIdx.x * blockDim.x + threadIdx.x;
    const float4 v = ((const float4*)Y)[i];
    int c = (i * 4) & (N2V - 1);
    float4 o;
    o.x = fmaxf(fmaf(v.x, g_sc2[c+0], g_sh2[c+0]), 0.0f);
    o.y = fmaxf(fmaf(v.y, g_sc2[c+1], g_sh2[c+1]), 0.0f);
    o.z = fmaxf(fmaf(v.z, g_sc2[c+2], g_sh2[c+2]), 0.0f);
    o.w = fmaxf(fmaf(v.w, g_sc2[c+3], g_sh2[c+3]), 0.0f);
    ((float4*)out)[i] = o;
}

// ---------------------------------------------------------------------------
// Launcher (graph-capturable)
// ---------------------------------------------------------------------------
extern "C" void kernel_launch(void* const* d_in, const int* in_sizes, int n_in,
                              void* d_out, int out_size)
{
    const float* xyz1    = (const float*)d_in[0];
    const float* xyz2    = (const float*)d_in[1];
    const float* points1 = (const float*)d_in[2];
    const float* points2 = (const float*)d_in[3];
    const float* w1      = (const float*)d_in[4];
    const float* b1      = (const float*)d_in[5];
    const float* g1      = (const float*)d_in[6];
    const float* beta1   = (const float*)d_in[7];
    const float* w2      = (const float*)d_in[8];
    const float* b2      = (const float*)d_in[9];
    const float* g2      = (const float*)d_in[10];
    const float* beta2   = (const float*)d_in[11];
    float* out = (float*)d_out;

    float *pX, *pY1, *pY2, *pps1, *ppq1, *pps2, *ppq2, *psc1, *psh1, *psc2, *psh2;
    cudaGetSymbolAddress((void**)&pX,   g_X);
    cudaGetSymbolAddress((void**)&pY1,  g_Y1);
    cudaGetSymbolAddress((void**)&pY2,  g_Y2);
    cudaGetSymbolAddress((void**)&pps1, g_ps1);
    cudaGetSymbolAddress((void**)&ppq1, g_pq1);
    cudaGetSymbolAddress((void**)&pps2, g_ps2);
    cudaGetSymbolAddress((void**)&ppq2, g_pq2);
    cudaGetSymbolAddress((void**)&psc1, g_sc1);
    cudaGetSymbolAddress((void**)&psh1, g_sh1);
    cudaGetSymbolAddress((void**)&psc2, g_sc2);
    cudaGetSymbolAddress((void**)&psh2, g_sh2);

    const int SMEM = 768*4 + 2 * BUF_WRD * 4;    // 52224 B
    cudaFuncSetAttribute(gemm_mma<K1V, false>,
                         cudaFuncAttributeMaxDynamicSharedMemorySize, SMEM);
    cudaFuncSetAttribute(gemm_mma<K2V, true>,
                         cudaFuncAttributeMaxDynamicSharedMemorySize, SMEM);

    nn3_kernel<<<dim3(NPTS/256, BATCH), 256>>>(xyz1, xyz2);
    gather_concat_kernel<<<MROWS/8, 256>>>(points1, points2);

    gemm_mma<K1V, false><<<dim3(N1V/128, MROWS/128), 256, SMEM>>>(
        pX, w1, b1, nullptr, nullptr, pY1, pps1, ppq1, N1V);
    bn_stats2<<<N1V, 128>>>(pps1, ppq1, g1, beta1, psc1, psh1);

    gemm_mma<K2V, true><<<dim3(N2V/128, MROWS/128), 256, SMEM>>>(
        pY1, w2, b2, psc1, psh1, pY2, pps2, ppq2, N2V);
    bn_stats2<<<N2V, 128>>>(pps2, ppq2, g2, beta2, psc2, psh2);

    bn_relu_out_kernel<<<(MROWS * N2V / 4) / 256, 256>>>(pY2, out);
}

// round 13
// speedup vs baseline: 1.1089x; 1.0737x over previous
#include <cuda_runtime.h>
#include <cuda_fp16.h>
#include <math.h>
#include <stdint.h>

// Problem constants
#define BATCH 8
#define NPTS  8192
#define SPTS  2048
#define C1V   128
#define C2V   256
#define MROWS 65536
#define K1V   384
#define N1V   256
#define K2V   256
#define N2V   128
#define RPARTS 512            // one partial per 128-row GEMM tile

// Scratch (device globals: allocation-free)
__device__ float g_X [(size_t)MROWS * K1V];
__device__ float g_Y1[(size_t)MROWS * N1V];
__device__ float g_Y2[(size_t)MROWS * N2V];
__device__ int   g_idx[MROWS * 3];
__device__ float g_wt [MROWS * 3];
__device__ float g_ps1[N1V * RPARTS], g_pq1[N1V * RPARTS];   // [col][rowtile]
__device__ float g_ps2[N2V * RPARTS], g_pq2[N2V * RPARTS];
__device__ float g_sc1[N1V], g_sh1[N1V];
__device__ float g_sc2[N2V], g_sh2[N2V];

// ---------------------------------------------------------------------------
// fp16 / mma helpers
// ---------------------------------------------------------------------------
__device__ __forceinline__ uint32_t smem_u32(const void* p) {
    uint32_t a;
    asm("{ .reg .u64 t; cvta.to.shared.u64 t, %1; cvt.u32.u64 %0, t; }"
        : "=r"(a) : "l"(p));
    return a;
}
// a = ah + al in fp16 (captures ~22 mantissa bits of a)
__device__ __forceinline__ void split_pack_fp16(float e, float o,
                                                uint32_t& h, uint32_t& l) {
    __half he = __float2half_rn(e);
    __half ho = __float2half_rn(o);
    float re = e - __half2float(he);
    float ro = o - __half2float(ho);
    __half2 hp = __halves2half2(he, ho);
    __half2 lp = __floats2half2_rn(re, ro);
    h = *(uint32_t*)&hp;
    l = *(uint32_t*)&lp;
}
__device__ __forceinline__ uint32_t pack_fp16(float e, float o) {
    __half2 p = __floats2half2_rn(e, o);
    return *(uint32_t*)&p;
}
__device__ __forceinline__ void mma16(float* c, const uint32_t* a,
                                      uint32_t b0, uint32_t b1) {
    asm volatile(
        "mma.sync.aligned.m16n8k16.row.col.f32.f16.f16.f32 "
        "{%0,%1,%2,%3}, {%4,%5,%6,%7}, {%8,%9}, {%0,%1,%2,%3};"
        : "+f"(c[0]), "+f"(c[1]), "+f"(c[2]), "+f"(c[3])
        : "r"(a[0]), "r"(a[1]), "r"(a[2]), "r"(a[3]), "r"(b0), "r"(b1));
}
__device__ __forceinline__ void ldsm_x4(uint32_t* r, uint32_t addr) {
    asm volatile(
        "ldmatrix.sync.aligned.m8n8.x4.shared.b16 {%0,%1,%2,%3}, [%4];"
        : "=r"(r[0]), "=r"(r[1]), "=r"(r[2]), "=r"(r[3]) : "r"(addr));
}

// ---------------------------------------------------------------------------
// Kernel 1: 3-NN + interpolation weights (3-FMA inner loop)
// ---------------------------------------------------------------------------
__global__ void nn3_kernel(const float* __restrict__ xyz1,
                           const float* __restrict__ xyz2)
{
    __shared__ float4 s2[SPTS];
    const int b = blockIdx.y;
    const float* x2 = xyz2 + (size_t)b * SPTS * 3;
    for (int i = threadIdx.x; i < SPTS; i += blockDim.x) {
        float x = x2[i*3+0], y = x2[i*3+1], z = x2[i*3+2];
        s2[i] = make_float4(x, y, z, 0.5f*(x*x + y*y + z*z));
    }
    __syncthreads();

    const int n = blockIdx.x * blockDim.x + threadIdx.x;
    const int p = b * NPTS + n;
    const float ax = xyz1[(size_t)p*3+0];
    const float ay = xyz1[(size_t)p*3+1];
    const float az = xyz1[(size_t)p*3+2];
    const float an = ax*ax + ay*ay + az*az;

    float e0 = 1e30f, e1 = 1e30f, e2 = 1e30f;
    int   j0 = 0,     j1 = 0,     j2 = 0;
    #pragma unroll 8
    for (int s = 0; s < SPTS; s++) {
        float4 q = s2[s];
        float ee = fmaf(-ax, q.x, fmaf(-ay, q.y, fmaf(-az, q.z, q.w)));
        if (ee < e2) {
            if (ee < e1) {
                if (ee < e0) { e2=e1; j2=j1; e1=e0; j1=j0; e0=ee; j0=s; }
                else         { e2=e1; j2=j1; e1=ee; j1=s; }
            } else           { e2=ee; j2=s; }
        }
    }
    float d0 = sqrtf(fmaxf(fmaf(2.0f, e0, an), 0.0f));
    float d1 = sqrtf(fmaxf(fmaf(2.0f, e1, an), 0.0f));
    float d2 = sqrtf(fmaxf(fmaf(2.0f, e2, an), 0.0f));
    float r0 = 1.0f / (d0 + 1e-8f);
    float r1 = 1.0f / (d1 + 1e-8f);
    float r2 = 1.0f / (d2 + 1e-8f);
    float inv = 1.0f / (r0 + r1 + r2);
    g_wt[p*3+0] = r0*inv; g_wt[p*3+1] = r1*inv; g_wt[p*3+2] = r2*inv;
    g_idx[p*3+0] = j0;    g_idx[p*3+1] = j1;    g_idx[p*3+2] = j2;
}

// ---------------------------------------------------------------------------
// Kernel 2: X = [points1 | interp(points2)]  ([MROWS, 384], fp32)
// ---------------------------------------------------------------------------
__global__ void gather_concat_kernel(const float* __restrict__ points1,
                                     const float* __restrict__ points2)
{
    const int warp = threadIdx.x >> 5;
    const int lane = threadIdx.x & 31;
    const int p = blockIdx.x * 8 + warp;
    const int b = p >> 13;

    const int   i0 = g_idx[p*3+0], i1 = g_idx[p*3+1], i2 = g_idx[p*3+2];
    const float w0 = g_wt[p*3+0],  w1 = g_wt[p*3+1],  w2 = g_wt[p*3+2];

    const float4* p1 = (const float4*)(points1 + (size_t)p * C1V);
    float4* Xr = (float4*)(g_X + (size_t)p * K1V);
    Xr[lane] = p1[lane];

    const float4* pa = (const float4*)(points2 + ((size_t)b*SPTS + i0) * C2V);
    const float4* pb = (const float4*)(points2 + ((size_t)b*SPTS + i1) * C2V);
    const float4* pc = (const float4*)(points2 + ((size_t)b*SPTS + i2) * C2V);
    #pragma unroll
    for (int t = 0; t < 2; t++) {
        int c = t*32 + lane;
        float4 va = pa[c], vb = pb[c], vc = pc[c];
        float4 o;
        o.x = w0*va.x + w1*vb.x + w2*vc.x;
        o.y = w0*va.y + w1*vb.y + w2*vc.y;
        o.z = w0*va.z + w1*vb.z + w2*vc.z;
        o.w = w0*va.w + w1*vb.w + w2*vc.w;
        Xr[32 + c] = o;
    }
}

// ---------------------------------------------------------------------------
// fp16x2 m16n8k16 GEMM (R12 pipeline; 2 MMA terms instead of 3):
//   y = (ah + al) * bh   (A split in fp16 ~exact; B rounded once to fp16,
//   per-element rel err <= 2^-11 -> aggregate rel err ~3e-4 << 1e-3)
// CTA 128x128, BK=16, 8 warps (4m x 2n), warp tile 32x64, double-buffered,
// 2 CTAs/SM, LDSM fragment loads, term-major HMMA passes.
// smem per buffer: Ah | Al | Bh (3 tiles; Bl is gone).
// Epilogue: +bias, Y store, fused BN partials (TRANSPOSED [col][rowtile]).
// TRANS_A fuses relu(a*scale+shift) (previous BN) into the A global load.
// ---------------------------------------------------------------------------
#define TROW_W 12                      // uint32 words per tile row
#define TILE_WRD (128 * TROW_W)
#define BUF_WRD (3 * TILE_WRD)         // Ah|Al|Bh per buffer

template<int KDIM, bool TRANS_A>
__global__ void __launch_bounds__(256, 2)
gemm_mma(const float* __restrict__ A,
         const float* __restrict__ W,
         const float* __restrict__ bias,
         const float* __restrict__ aScale,
         const float* __restrict__ aShift,
         float* __restrict__ Y,
         float* __restrict__ psum,
         float* __restrict__ psq,
         int N)
{
    extern __shared__ float sm[];
    float* sSc = sm;                    // [384]
    float* sSh = sm + 384;              // [384]
    uint32_t* tiles = (uint32_t*)(sm + 768);

    const int tid  = threadIdx.x;
    const int wid  = tid >> 5;
    const int lane = tid & 31;
    const int lg   = lane >> 2;
    const int lt   = lane & 3;
    const int wm   = (wid & 3) * 32;
    const int wn   = (wid >> 2) * 64;

    // ldmatrix per-lane addressing (bytes)
    const uint32_t tilesAddr = smem_u32(tiles);
    const int aRow = lane & 15;
    const int aOff = (lane >> 4) * 16;
    const int bRow = (lane & 7) + ((lane >> 4) << 3);
    const int bOff = ((lane >> 3) & 1) * 16;

    if (TRANS_A) {
        for (int i = tid; i < KDIM; i += 256) { sSc[i] = aScale[i]; sSh[i] = aShift[i]; }
        __syncthreads();
    }

    float acc[2][8][4];
    #pragma unroll
    for (int mt = 0; mt < 2; mt++)
        #pragma unroll
        for (int nt = 0; nt < 8; nt++)
            #pragma unroll
            for (int j = 0; j < 4; j++) acc[mt][nt][j] = 0.0f;

    const float* Ab = A + (size_t)blockIdx.y * 128 * KDIM;
    const float* Wb = W + (size_t)blockIdx.x * 128 * KDIM;

    const int r = tid >> 2;            // 0..63
    const int q = tid & 3;             // float4 slot within k16

    float4 av[2], wv[2];
    auto g_load = [&](int k0) {
        #pragma unroll
        for (int i = 0; i < 2; i++) {
            int rr = i*64 + r;
            float4 v = *(const float4*)(Ab + (size_t)rr*KDIM + k0 + q*4);
            if (TRANS_A) {
                int kb = k0 + q*4;
                v.x = fmaxf(fmaf(v.x, sSc[kb+0], sSh[kb+0]), 0.0f);
                v.y = fmaxf(fmaf(v.y, sSc[kb+1], sSh[kb+1]), 0.0f);
                v.z = fmaxf(fmaf(v.z, sSc[kb+2], sSh[kb+2]), 0.0f);
                v.w = fmaxf(fmaf(v.w, sSc[kb+3], sSh[kb+3]), 0.0f);
            }
            av[i] = v;
            wv[i] = *(const float4*)(Wb + (size_t)rr*KDIM + k0 + q*4);
        }
    };
    auto s_store = [&](int buf) {
        uint32_t* base = tiles + buf * BUF_WRD;
        #pragma unroll
        for (int i = 0; i < 2; i++) {
            const int rr = i*64 + r;
            const int wo = rr * TROW_W + q*2;
            uint32_t h0, l0, h1, l1;
            split_pack_fp16(av[i].x, av[i].y, h0, l0);
            split_pack_fp16(av[i].z, av[i].w, h1, l1);
            *(uint2*)(base + wo)              = make_uint2(h0, h1);  // Ah
            *(uint2*)(base + TILE_WRD + wo)   = make_uint2(l0, l1);  // Al
            const uint32_t bh0 = pack_fp16(wv[i].x, wv[i].y);
            const uint32_t bh1 = pack_fp16(wv[i].z, wv[i].w);
            *(uint2*)(base + 2*TILE_WRD + wo) = make_uint2(bh0, bh1); // Bh
        }
    };
    auto do_mma = [&](int buf) {
        const uint32_t tb = tilesAddr + buf * (BUF_WRD * 4);
        uint32_t ahr[2][4], alr[2][4];
        #pragma unroll
        for (int mt = 0; mt < 2; mt++) {
            const uint32_t ad = tb + (uint32_t)((wm + mt*16 + aRow) * TROW_W) * 4 + aOff;
            ldsm_x4(ahr[mt], ad);
            ldsm_x4(alr[mt], ad + TILE_WRD * 4);
        }
        #pragma unroll
        for (int half = 0; half < 2; half++) {
            uint32_t bh[2][4];
            #pragma unroll
            for (int g = 0; g < 2; g++) {
                const int ntp = half*2 + g;
                const uint32_t bd = tb + 2*TILE_WRD*4
                    + (uint32_t)((wn + ntp*16 + bRow) * TROW_W) * 4 + bOff;
                ldsm_x4(bh[g], bd);
            }
            // pass 1: ah * bh  (8 independent HMMAs)
            #pragma unroll
            for (int g = 0; g < 2; g++)
                #pragma unroll
                for (int s = 0; s < 2; s++)
                    #pragma unroll
                    for (int mt = 0; mt < 2; mt++)
                        mma16(acc[mt][half*4 + g*2 + s], ahr[mt],
                              bh[g][2*s], bh[g][2*s+1]);
            // pass 2: al * bh
            #pragma unroll
            for (int g = 0; g < 2; g++)
                #pragma unroll
                for (int s = 0; s < 2; s++)
                    #pragma unroll
                    for (int mt = 0; mt < 2; mt++)
                        mma16(acc[mt][half*4 + g*2 + s], alr[mt],
                              bh[g][2*s], bh[g][2*s+1]);
        }
    };

    const int KT = KDIM / 16;
    g_load(0);
    s_store(0);
    __syncthreads();
    for (int kt = 0; kt < KT; kt++) {
        if (kt + 1 < KT) g_load((kt + 1) * 16);
        do_mma(kt & 1);
        if (kt + 1 < KT) {
            s_store((kt + 1) & 1);
            __syncthreads();
        }
    }

    // ---- Epilogue: +bias, store Y, fused BN partial stats
    #pragma unroll
    for (int nt = 0; nt < 8; nt++) {
        const int col = blockIdx.x*128 + wn + nt*8 + 2*lt;
        const float b0 = __ldg(&bias[col]), b1 = __ldg(&bias[col+1]);
        #pragma unroll
        for (int mt = 0; mt < 2; mt++) {
            acc[mt][nt][0] += b0; acc[mt][nt][1] += b1;
            acc[mt][nt][2] += b0; acc[mt][nt][3] += b1;
            const int row0 = blockIdx.y*128 + wm + mt*16 + lg;
            *(float2*)(Y + (size_t)row0 * N + col) =
                make_float2(acc[mt][nt][0], acc[mt][nt][1]);
            *(float2*)(Y + (size_t)(row0+8) * N + col) =
                make_float2(acc[mt][nt][2], acc[mt][nt][3]);
        }
    }

    __syncthreads();                      // reuse tiles as reduction space
    float* srs = (float*)tiles;
    float* srq = (float*)tiles + 512;
    #pragma unroll
    for (int nt = 0; nt < 8; nt++) {
        float sA = acc[0][nt][0] + acc[0][nt][2] + acc[1][nt][0] + acc[1][nt][2];
        float sB = acc[0][nt][1] + acc[0][nt][3] + acc[1][nt][1] + acc[1][nt][3];
        float qA = acc[0][nt][0]*acc[0][nt][0] + acc[0][nt][2]*acc[0][nt][2]
                 + acc[1][nt][0]*acc[1][nt][0] + acc[1][nt][2]*acc[1][nt][2];
        float qB = acc[0][nt][1]*acc[0][nt][1] + acc[0][nt][3]*acc[0][nt][3]
                 + acc[1][nt][1]*acc[1][nt][1] + acc[1][nt][3]*acc[1][nt][3];
        #pragma unroll
        for (int o = 4; o <= 16; o <<= 1) {
            sA += __shfl_xor_sync(0xFFFFFFFFu, sA, o);
            sB += __shfl_xor_sync(0xFFFFFFFFu, sB, o);
            qA += __shfl_xor_sync(0xFFFFFFFFu, qA, o);
            qB += __shfl_xor_sync(0xFFFFFFFFu, qB, o);
        }
        if (lane < 4) {
            srs[wid*64 + nt*8 + lane*2 + 0] = sA;
            srs[wid*64 + nt*8 + lane*2 + 1] = sB;
            srq[wid*64 + nt*8 + lane*2 + 0] = qA;
            srq[wid*64 + nt*8 + lane*2 + 1] = qB;
        }
    }
    __syncthreads();
    if (tid < 128) {
        const int w0 = tid >> 6, cc = tid & 63;
        float s = 0.0f, qq = 0.0f;
        #pragma unroll
        for (int k = 0; k < 4; k++) {
            s  += srs[(w0*4 + k)*64 + cc];
            qq += srq[(w0*4 + k)*64 + cc];
        }
        // transposed: [col][rowtile] -> contiguous per-channel reduction
        const size_t o = (size_t)(blockIdx.x*128 + tid) * RPARTS + blockIdx.y;
        psum[o] = s;
        psq [o] = qq;
    }
}

// ---------------------------------------------------------------------------
// BN stats stage 2: one block per channel; 512 contiguous partials.
// ---------------------------------------------------------------------------
__global__ void bn_stats2(const float* __restrict__ ps, const float* __restrict__ pq,
                          const float* __restrict__ g,
                          const float* __restrict__ beta,
                          float* __restrict__ scale, float* __restrict__ shift)
{
    __shared__ float ss[4], sq[4];
    const int c = blockIdx.x, tid = threadIdx.x;   // 128 threads
    float4 v = ((const float4*)(ps + (size_t)c * RPARTS))[tid];
    float4 w = ((const float4*)(pq + (size_t)c * RPARTS))[tid];
    float s = (v.x + v.y) + (v.z + v.w);
    float q = (w.x + w.y) + (w.z + w.w);
    #pragma unroll
    for (int o = 16; o >= 1; o >>= 1) {
        s += __shfl_down_sync(0xFFFFFFFFu, s, o);
        q += __shfl_down_sync(0xFFFFFFFFu, q, o);
    }
    if ((tid & 31) == 0) { ss[tid >> 5] = s; sq[tid >> 5] = q; }
    __syncthreads();
    if (tid == 0) {
        double S = ((double)ss[0] + (double)ss[1]) + ((double)ss[2] + (double)ss[3]);
        double Q = ((double)sq[0] + (double)sq[1]) + ((double)sq[2] + (double)sq[3]);
        double mu  = S / (double)MROWS;
        double var = Q / (double)MROWS - mu * mu;
        float sc = g[c] / sqrtf((float)var + 1e-5f);
        scale[c] = sc;
        shift[c] = beta[c] - (float)mu * sc;
    }
}

// ---------------------------------------------------------------------------
// Final: out = relu(Y2 * scale2 + shift2)
// ---------------------------------------------------------------------------
__global__ void bn_relu_out_kernel(const float* __restrict__ Y,
                                   float* __restrict__ out)
{
    int i = blockIdx.x * blockDim.x + threadIdx.x;
    const float4 v = ((const float4*)Y)[i];
    int c = (i * 4) & (N2V - 1);
    float4 o;
    o.x = fmaxf(fmaf(v.x, g_sc2[c+0], g_sh2[c+0]), 0.0f);
    o.y = fmaxf(fmaf(v.y, g_sc2[c+1], g_sh2[c+1]), 0.0f);
    o.z = fmaxf(fmaf(v.z, g_sc2[c+2], g_sh2[c+2]), 0.0f);
    o.w = fmaxf(fmaf(v.w, g_sc2[c+3], g_sh2[c+3]), 0.0f);
    ((float4*)out)[i] = o;
}

// ---------------------------------------------------------------------------
// Launcher (graph-capturable)
// ---------------------------------------------------------------------------
extern "C" void kernel_launch(void* const* d_in, const int* in_sizes, int n_in,
                              void* d_out, int out_size)
{
    const float* xyz1    = (const float*)d_in[0];
    const float* xyz2    = (const float*)d_in[1];
    const float* points1 = (const float*)d_in[2];
    const float* points2 = (const float*)d_in[3];
    const float* w1      = (const float*)d_in[4];
    const float* b1      = (const float*)d_in[5];
    const float* g1      = (const float*)d_in[6];
    const float* beta1   = (const float*)d_in[7];
    const float* w2      = (const float*)d_in[8];
    const float* b2      = (const float*)d_in[9];
    const float* g2      = (const float*)d_in[10];
    const float* beta2   = (const float*)d_in[11];
    float* out = (float*)d_out;

    float *pX, *pY1, *pY2, *pps1, *ppq1, *pps2, *ppq2, *psc1, *psh1, *psc2, *psh2;
    cudaGetSymbolAddress((void**)&pX,   g_X);
    cudaGetSymbolAddress((void**)&pY1,  g_Y1);
    cudaGetSymbolAddress((void**)&pY2,  g_Y2);
    cudaGetSymbolAddress((void**)&pps1, g_ps1);
    cudaGetSymbolAddress((void**)&ppq1, g_pq1);
    cudaGetSymbolAddress((void**)&pps2, g_ps2);
    cudaGetSymbolAddress((void**)&ppq2, g_pq2);
    cudaGetSymbolAddress((void**)&psc1, g_sc1);
    cudaGetSymbolAddress((void**)&psh1, g_sh1);
    cudaGetSymbolAddress((void**)&psc2, g_sc2);
    cudaGetSymbolAddress((void**)&psh2, g_sh2);

    const int SMEM = 768*4 + 2 * BUF_WRD * 4;    // 3072 + 36864 = 39936 B
    cudaFuncSetAttribute(gemm_mma<K1V, false>,
                         cudaFuncAttributeMaxDynamicSharedMemorySize, SMEM);
    cudaFuncSetAttribute(gemm_mma<K2V, true>,
                         cudaFuncAttributeMaxDynamicSharedMemorySize, SMEM);

    nn3_kernel<<<dim3(NPTS/256, BATCH), 256>>>(xyz1, xyz2);
    gather_concat_kernel<<<MROWS/8, 256>>>(points1, points2);

    gemm_mma<K1V, false><<<dim3(N1V/128, MROWS/128), 256, SMEM>>>(
        pX, w1, b1, nullptr, nullptr, pY1, pps1, ppq1, N1V);
    bn_stats2<<<N1V, 128>>>(pps1, ppq1, g1, beta1, psc1, psh1);

    gemm_mma<K2V, true><<<dim3(N2V/128, MROWS/128), 256, SMEM>>>(
        pY1, w2, b2, psc1, psh1, pY2, pps2, ppq2, N2V);
    bn_stats2<<<N2V, 128>>>(pps2, ppq2, g2, beta2, psc2, psh2);

    bn_relu_out_kernel<<<(MROWS * N2V / 4) / 256, 256>>>(pY2, out);
}

// round 14
// speedup vs baseline: 1.3219x; 1.1921x over previous
#include <cuda_runtime.h>
#include <cuda_fp16.h>
#include <math.h>
#include <stdint.h>

// Problem constants
#define BATCH 8
#define NPTS  8192
#define SPTS  2048
#define C1V   128
#define C2V   256
#define MROWS 65536
#define K1V   384
#define N1V   256
#define K2V   256
#define N2V   128
#define RPARTS 512            // one partial per 128-row GEMM tile

// Scratch (device globals: allocation-free)
__device__ float g_Z [(size_t)BATCH * SPTS * N1V];   // P2 @ W1b^T  (16 MB)
__device__ float g_ZI[(size_t)MROWS * N1V];          // interpolated Z (64 MB)
__device__ float g_Y1[(size_t)MROWS * N1V];
__device__ float g_Y2[(size_t)MROWS * N2V];
__device__ int   g_idx[MROWS * 3];
__device__ float g_wt [MROWS * 3];
__device__ float g_ps1[N1V * RPARTS], g_pq1[N1V * RPARTS];   // [col][rowtile]
__device__ float g_ps2[N2V * RPARTS], g_pq2[N2V * RPARTS];
__device__ float g_sc1[N1V], g_sh1[N1V];
__device__ float g_sc2[N2V], g_sh2[N2V];

// ---------------------------------------------------------------------------
// fp16 / mma helpers
// ---------------------------------------------------------------------------
__device__ __forceinline__ uint32_t smem_u32(const void* p) {
    uint32_t a;
    asm("{ .reg .u64 t; cvta.to.shared.u64 t, %1; cvt.u32.u64 %0, t; }"
        : "=r"(a) : "l"(p));
    return a;
}
// a = ah + al in fp16 (captures ~22 mantissa bits of a)
__device__ __forceinline__ void split_pack_fp16(float e, float o,
                                                uint32_t& h, uint32_t& l) {
    __half he = __float2half_rn(e);
    __half ho = __float2half_rn(o);
    float re = e - __half2float(he);
    float ro = o - __half2float(ho);
    __half2 hp = __halves2half2(he, ho);
    __half2 lp = __floats2half2_rn(re, ro);
    h = *(uint32_t*)&hp;
    l = *(uint32_t*)&lp;
}
__device__ __forceinline__ uint32_t pack_fp16(float e, float o) {
    __half2 p = __floats2half2_rn(e, o);
    return *(uint32_t*)&p;
}
__device__ __forceinline__ void mma16(float* c, const uint32_t* a,
                                      uint32_t b0, uint32_t b1) {
    asm volatile(
        "mma.sync.aligned.m16n8k16.row.col.f32.f16.f16.f32 "
        "{%0,%1,%2,%3}, {%4,%5,%6,%7}, {%8,%9}, {%0,%1,%2,%3};"
        : "+f"(c[0]), "+f"(c[1]), "+f"(c[2]), "+f"(c[3])
        : "r"(a[0]), "r"(a[1]), "r"(a[2]), "r"(a[3]), "r"(b0), "r"(b1));
}
__device__ __forceinline__ void ldsm_x4(uint32_t* r, uint32_t addr) {
    asm volatile(
        "ldmatrix.sync.aligned.m8n8.x4.shared.b16 {%0,%1,%2,%3}, [%4];"
        : "=r"(r[0]), "=r"(r[1]), "=r"(r[2]), "=r"(r[3]) : "r"(addr));
}

// ---------------------------------------------------------------------------
// Kernel 1: 3-NN + interpolation weights (3-FMA inner loop)
// ---------------------------------------------------------------------------
__global__ void nn3_kernel(const float* __restrict__ xyz1,
                           const float* __restrict__ xyz2)
{
    __shared__ float4 s2[SPTS];
    const int b = blockIdx.y;
    const float* x2 = xyz2 + (size_t)b * SPTS * 3;
    for (int i = threadIdx.x; i < SPTS; i += blockDim.x) {
        float x = x2[i*3+0], y = x2[i*3+1], z = x2[i*3+2];
        s2[i] = make_float4(x, y, z, 0.5f*(x*x + y*y + z*z));
    }
    __syncthreads();

    const int n = blockIdx.x * blockDim.x + threadIdx.x;
    const int p = b * NPTS + n;
    const float ax = xyz1[(size_t)p*3+0];
    const float ay = xyz1[(size_t)p*3+1];
    const float az = xyz1[(size_t)p*3+2];
    const float an = ax*ax + ay*ay + az*az;

    float e0 = 1e30f, e1 = 1e30f, e2 = 1e30f;
    int   j0 = 0,     j1 = 0,     j2 = 0;
    #pragma unroll 8
    for (int s = 0; s < SPTS; s++) {
        float4 q = s2[s];
        float ee = fmaf(-ax, q.x, fmaf(-ay, q.y, fmaf(-az, q.z, q.w)));
        if (ee < e2) {
            if (ee < e1) {
                if (ee < e0) { e2=e1; j2=j1; e1=e0; j1=j0; e0=ee; j0=s; }
                else         { e2=e1; j2=j1; e1=ee; j1=s; }
            } else           { e2=ee; j2=s; }
        }
    }
    float d0 = sqrtf(fmaxf(fmaf(2.0f, e0, an), 0.0f));
    float d1 = sqrtf(fmaxf(fmaf(2.0f, e1, an), 0.0f));
    float d2 = sqrtf(fmaxf(fmaf(2.0f, e2, an), 0.0f));
    float r0 = 1.0f / (d0 + 1e-8f);
    float r1 = 1.0f / (d1 + 1e-8f);
    float r2 = 1.0f / (d2 + 1e-8f);
    float inv = 1.0f / (r0 + r1 + r2);
    g_wt[p*3+0] = r0*inv; g_wt[p*3+1] = r1*inv; g_wt[p*3+2] = r2*inv;
    g_idx[p*3+0] = j0;    g_idx[p*3+1] = j1;    g_idx[p*3+2] = j2;
}

// ---------------------------------------------------------------------------
// Kernel 2: ZI[p,:] = w0*Z[i0] + w1*Z[i1] + w2*Z[i2]  (Z is L2-resident 16MB)
// One warp per point; 256 floats per row.
// ---------------------------------------------------------------------------
__global__ void interpZ_kernel(const float* __restrict__ Z,
                               float* __restrict__ ZI)
{
    const int warp = threadIdx.x >> 5;
    const int lane = threadIdx.x & 31;
    const int p = blockIdx.x * 8 + warp;
    const int b = p >> 13;

    const int   i0 = g_idx[p*3+0], i1 = g_idx[p*3+1], i2 = g_idx[p*3+2];
    const float w0 = g_wt[p*3+0],  w1 = g_wt[p*3+1],  w2 = g_wt[p*3+2];

    const float4* za = (const float4*)(Z + ((size_t)b*SPTS + i0) * N1V);
    const float4* zb = (const float4*)(Z + ((size_t)b*SPTS + i1) * N1V);
    const float4* zc = (const float4*)(Z + ((size_t)b*SPTS + i2) * N1V);
    float4* out = (float4*)(ZI + (size_t)p * N1V);
    #pragma unroll
    for (int t = 0; t < 2; t++) {
        int c = t*32 + lane;
        float4 va = za[c], vb = zb[c], vc = zc[c];
        float4 o;
        o.x = w0*va.x + w1*vb.x + w2*vc.x;
        o.y = w0*va.y + w1*vb.y + w2*vc.y;
        o.z = w0*va.z + w1*vb.z + w2*vc.z;
        o.w = w0*va.w + w1*vb.w + w2*vc.w;
        out[c] = o;
    }
}

// ---------------------------------------------------------------------------
// fp16x2 m16n8k16 GEMM (R13 pipeline) with row strides + optional addend:
//   Y[M,N] = op(A)[M,K] @ W[N,K]^T (+ bias) (+ addY)
// y = (ah + al) * bh. CTA 128x128, BK=16, 8 warps, warp tile 32x64,
// double-buffered, 2 CTAs/SM, LDSM loads, term-major HMMA passes.
// lda/ldw: row strides (lets W slice columns of w1). bias may be null.
// HAS_ADD: epilogue adds addY[row,col] (the interpolated Z term).
// psum==nullptr skips the fused BN-stats epilogue (Z GEMM).
// TRANS_A fuses relu(a*scale+shift) (previous BN) into the A global load.
// ---------------------------------------------------------------------------
#define TROW_W 12                      // uint32 words per tile row
#define TILE_WRD (128 * TROW_W)
#define BUF_WRD (3 * TILE_WRD)         // Ah|Al|Bh per buffer

template<int KDIM, bool TRANS_A, bool HAS_ADD>
__global__ void __launch_bounds__(256, 2)
gemm_mma(const float* __restrict__ A, int lda,
         const float* __restrict__ W, int ldw,
         const float* __restrict__ bias,
         const float* __restrict__ aScale,
         const float* __restrict__ aShift,
         const float* __restrict__ addY,
         float* __restrict__ Y,
         float* __restrict__ psum,
         float* __restrict__ psq,
         int N)
{
    extern __shared__ float sm[];
    float* sSc = sm;                    // [KDIM]
    float* sSh = sm + 384;              // [KDIM]
    uint32_t* tiles = (uint32_t*)(sm + 768);

    const int tid  = threadIdx.x;
    const int wid  = tid >> 5;
    const int lane = tid & 31;
    const int lg   = lane >> 2;
    const int lt   = lane & 3;
    const int wm   = (wid & 3) * 32;
    const int wn   = (wid >> 2) * 64;

    // ldmatrix per-lane addressing (bytes)
    const uint32_t tilesAddr = smem_u32(tiles);
    const int aRow = lane & 15;
    const int aOff = (lane >> 4) * 16;
    const int bRow = (lane & 7) + ((lane >> 4) << 3);
    const int bOff = ((lane >> 3) & 1) * 16;

    if (TRANS_A) {
        for (int i = tid; i < KDIM; i += 256) { sSc[i] = aScale[i]; sSh[i] = aShift[i]; }
        __syncthreads();
    }

    float acc[2][8][4];
    #pragma unroll
    for (int mt = 0; mt < 2; mt++)
        #pragma unroll
        for (int nt = 0; nt < 8; nt++)
            #pragma unroll
            for (int j = 0; j < 4; j++) acc[mt][nt][j] = 0.0f;

    const float* Ab = A + (size_t)blockIdx.y * 128 * lda;
    const float* Wb = W + (size_t)blockIdx.x * 128 * ldw;

    const int r = tid >> 2;            // 0..63
    const int q = tid & 3;             // float4 slot within k16

    float4 av[2], wv[2];
    auto g_load = [&](int k0) {
        #pragma unroll
        for (int i = 0; i < 2; i++) {
            int rr = i*64 + r;
            float4 v = *(const float4*)(Ab + (size_t)rr*lda + k0 + q*4);
            if (TRANS_A) {
                int kb = k0 + q*4;
                v.x = fmaxf(fmaf(v.x, sSc[kb+0], sSh[kb+0]), 0.0f);
                v.y = fmaxf(fmaf(v.y, sSc[kb+1], sSh[kb+1]), 0.0f);
                v.z = fmaxf(fmaf(v.z, sSc[kb+2], sSh[kb+2]), 0.0f);
                v.w = fmaxf(fmaf(v.w, sSc[kb+3], sSh[kb+3]), 0.0f);
            }
            av[i] = v;
            wv[i] = *(const float4*)(Wb + (size_t)rr*ldw + k0 + q*4);
        }
    };
    auto s_store = [&](int buf) {
        uint32_t* base = tiles + buf * BUF_WRD;
        #pragma unroll
        for (int i = 0; i < 2; i++) {
            const int rr = i*64 + r;
            const int wo = rr * TROW_W + q*2;
            uint32_t h0, l0, h1, l1;
            split_pack_fp16(av[i].x, av[i].y, h0, l0);
            split_pack_fp16(av[i].z, av[i].w, h1, l1);
            *(uint2*)(base + wo)              = make_uint2(h0, h1);  // Ah
            *(uint2*)(base + TILE_WRD + wo)   = make_uint2(l0, l1);  // Al
            const uint32_t bh0 = pack_fp16(wv[i].x, wv[i].y);
            const uint32_t bh1 = pack_fp16(wv[i].z, wv[i].w);
            *(uint2*)(base + 2*TILE_WRD + wo) = make_uint2(bh0, bh1); // Bh
        }
    };
    auto do_mma = [&](int buf) {
        const uint32_t tb = tilesAddr + buf * (BUF_WRD * 4);
        uint32_t ahr[2][4], alr[2][4];
        #pragma unroll
        for (int mt = 0; mt < 2; mt++) {
            const uint32_t ad = tb + (uint32_t)((wm + mt*16 + aRow) * TROW_W) * 4 + aOff;
            ldsm_x4(ahr[mt], ad);
            ldsm_x4(alr[mt], ad + TILE_WRD * 4);
        }
        #pragma unroll
        for (int half = 0; half < 2; half++) {
            uint32_t bh[2][4];
            #pragma unroll
            for (int g = 0; g < 2; g++) {
                const int ntp = half*2 + g;
                const uint32_t bd = tb + 2*TILE_WRD*4
                    + (uint32_t)((wn + ntp*16 + bRow) * TROW_W) * 4 + bOff;
                ldsm_x4(bh[g], bd);
            }
            #pragma unroll
            for (int g = 0; g < 2; g++)
                #pragma unroll
                for (int s = 0; s < 2; s++)
                    #pragma unroll
                    for (int mt = 0; mt < 2; mt++)
                        mma16(acc[mt][half*4 + g*2 + s], ahr[mt],
                              bh[g][2*s], bh[g][2*s+1]);
            #pragma unroll
            for (int g = 0; g < 2; g++)
                #pragma unroll
                for (int s = 0; s < 2; s++)
                    #pragma unroll
                    for (int mt = 0; mt < 2; mt++)
                        mma16(acc[mt][half*4 + g*2 + s], alr[mt],
                              bh[g][2*s], bh[g][2*s+1]);
        }
    };

    const int KT = KDIM / 16;
    g_load(0);
    s_store(0);
    __syncthreads();
    for (int kt = 0; kt < KT; kt++) {
        if (kt + 1 < KT) g_load((kt + 1) * 16);
        do_mma(kt & 1);
        if (kt + 1 < KT) {
            s_store((kt + 1) & 1);
            __syncthreads();
        }
    }

    // ---- Epilogue: (+bias) (+addY), store Y, optional fused BN partials
    #pragma unroll
    for (int nt = 0; nt < 8; nt++) {
        const int col = blockIdx.x*128 + wn + nt*8 + 2*lt;
        const float b0 = bias ? __ldg(&bias[col])   : 0.0f;
        const float b1 = bias ? __ldg(&bias[col+1]) : 0.0f;
        #pragma unroll
        for (int mt = 0; mt < 2; mt++) {
            const int row0 = blockIdx.y*128 + wm + mt*16 + lg;
            if (HAS_ADD) {
                const float2 z0 = *(const float2*)(addY + (size_t)row0 * N + col);
                const float2 z1 = *(const float2*)(addY + (size_t)(row0+8) * N + col);
                acc[mt][nt][0] += z0.x; acc[mt][nt][1] += z0.y;
                acc[mt][nt][2] += z1.x; acc[mt][nt][3] += z1.y;
            }
            acc[mt][nt][0] += b0; acc[mt][nt][1] += b1;
            acc[mt][nt][2] += b0; acc[mt][nt][3] += b1;
            *(float2*)(Y + (size_t)row0 * N + col) =
                make_float2(acc[mt][nt][0], acc[mt][nt][1]);
            *(float2*)(Y + (size_t)(row0+8) * N + col) =
                make_float2(acc[mt][nt][2], acc[mt][nt][3]);
        }
    }

    if (psum != nullptr) {                // uniform branch
        __syncthreads();                  // reuse tiles as reduction space
        float* srs = (float*)tiles;
        float* srq = (float*)tiles + 512;
        #pragma unroll
        for (int nt = 0; nt < 8; nt++) {
            float sA = acc[0][nt][0] + acc[0][nt][2] + acc[1][nt][0] + acc[1][nt][2];
            float sB = acc[0][nt][1] + acc[0][nt][3] + acc[1][nt][1] + acc[1][nt][3];
            float qA = acc[0][nt][0]*acc[0][nt][0] + acc[0][nt][2]*acc[0][nt][2]
                     + acc[1][nt][0]*acc[1][nt][0] + acc[1][nt][2]*acc[1][nt][2];
            float qB = acc[0][nt][1]*acc[0][nt][1] + acc[0][nt][3]*acc[0][nt][3]
                     + acc[1][nt][1]*acc[1][nt][1] + acc[1][nt][3]*acc[1][nt][3];
            #pragma unroll
            for (int o = 4; o <= 16; o <<= 1) {
                sA += __shfl_xor_sync(0xFFFFFFFFu, sA, o);
                sB += __shfl_xor_sync(0xFFFFFFFFu, sB, o);
                qA += __shfl_xor_sync(0xFFFFFFFFu, qA, o);
                qB += __shfl_xor_sync(0xFFFFFFFFu, qB, o);
            }
            if (lane < 4) {
                srs[wid*64 + nt*8 + lane*2 + 0] = sA;
                srs[wid*64 + nt*8 + lane*2 + 1] = sB;
                srq[wid*64 + nt*8 + lane*2 + 0] = qA;
                srq[wid*64 + nt*8 + lane*2 + 1] = qB;
            }
        }
        __syncthreads();
        if (tid < 128) {
            const int w0 = tid >> 6, cc = tid & 63;
            float s = 0.0f, qq = 0.0f;
            #pragma unroll
            for (int k = 0; k < 4; k++) {
                s  += srs[(w0*4 + k)*64 + cc];
                qq += srq[(w0*4 + k)*64 + cc];
            }
            // transposed: [col][rowtile] -> contiguous per-channel reduction
            const size_t o = (size_t)(blockIdx.x*128 + tid) * RPARTS + blockIdx.y;
            psum[o] = s;
            psq [o] = qq;
        }
    }
}

// ---------------------------------------------------------------------------
// BN stats stage 2: one block per channel; 512 contiguous partials.
// ---------------------------------------------------------------------------
__global__ void bn_stats2(const float* __restrict__ ps, const float* __restrict__ pq,
                          const float* __restrict__ g,
                          const float* __restrict__ beta,
                          float* __restrict__ scale, float* __restrict__ shift)
{
    __shared__ float ss[4], sq[4];
    const int c = blockIdx.x, tid = threadIdx.x;   // 128 threads
    float4 v = ((const float4*)(ps + (size_t)c * RPARTS))[tid];
    float4 w = ((const float4*)(pq + (size_t)c * RPARTS))[tid];
    float s = (v.x + v.y) + (v.z + v.w);
    float q = (w.x + w.y) + (w.z + w.w);
    #pragma unroll
    for (int o = 16; o >= 1; o >>= 1) {
        s += __shfl_down_sync(0xFFFFFFFFu, s, o);
        q += __shfl_down_sync(0xFFFFFFFFu, q, o);
    }
    if ((tid & 31) == 0) { ss[tid >> 5] = s; sq[tid >> 5] = q; }
    __syncthreads();
    if (tid == 0) {
        double S = ((double)ss[0] + (double)ss[1]) + ((double)ss[2] + (double)ss[3]);
        double Q = ((double)sq[0] + (double)sq[1]) + ((double)sq[2] + (double)sq[3]);
        double mu  = S / (double)MROWS;
        double var = Q / (double)MROWS - mu * mu;
        float sc = g[c] / sqrtf((float)var + 1e-5f);
        scale[c] = sc;
        shift[c] = beta[c] - (float)mu * sc;
    }
}

// ---------------------------------------------------------------------------
// Final: out = relu(Y2 * scale2 + shift2)
// ---------------------------------------------------------------------------
__global__ void bn_relu_out_kernel(const float* __restrict__ Y,
                                   float* __restrict__ out)
{
    int i = blockIdx.x * blockDim.x + threadIdx.x;
    const float4 v = ((const float4*)Y)[i];
    int c = (i * 4) & (N2V - 1);
    float4 o;
    o.x = fmaxf(fmaf(v.x, g_sc2[c+0], g_sh2[c+0]), 0.0f);
    o.y = fmaxf(fmaf(v.y, g_sc2[c+1], g_sh2[c+1]), 0.0f);
    o.z = fmaxf(fmaf(v.z, g_sc2[c+2], g_sh2[c+2]), 0.0f);
    o.w = fmaxf(fmaf(v.w, g_sc2[c+3], g_sh2[c+3]), 0.0f);
    ((float4*)out)[i] = o;
}

// ---------------------------------------------------------------------------
// Launcher (graph-capturable)
// ---------------------------------------------------------------------------
extern "C" void kernel_launch(void* const* d_in, const int* in_sizes, int n_in,
                              void* d_out, int out_size)
{
    const float* xyz1    = (const float*)d_in[0];
    const float* xyz2    = (const float*)d_in[1];
    const float* points1 = (const float*)d_in[2];
    const float* points2 = (const float*)d_in[3];
    const float* w1      = (const float*)d_in[4];
    const float* b1      = (const float*)d_in[5];
    const float* g1      = (const float*)d_in[6];
    const float* beta1   = (const float*)d_in[7];
    const float* w2      = (const float*)d_in[8];
    const float* b2      = (const float*)d_in[9];
    const float* g2      = (const float*)d_in[10];
    const float* beta2   = (const float*)d_in[11];
    float* out = (float*)d_out;

    float *pZ, *pZI, *pY1, *pY2, *pps1, *ppq1, *pps2, *ppq2, *psc1, *psh1, *psc2, *psh2;
    cudaGetSymbolAddress((void**)&pZ,   g_Z);
    cudaGetSymbolAddress((void**)&pZI,  g_ZI);
    cudaGetSymbolAddress((void**)&pY1,  g_Y1);
    cudaGetSymbolAddress((void**)&pY2,  g_Y2);
    cudaGetSymbolAddress((void**)&pps1, g_ps1);
    cudaGetSymbolAddress((void**)&ppq1, g_pq1);
    cudaGetSymbolAddress((void**)&pps2, g_ps2);
    cudaGetSymbolAddress((void**)&ppq2, g_pq2);
    cudaGetSymbolAddress((void**)&psc1, g_sc1);
    cudaGetSymbolAddress((void**)&psh1, g_sh1);
    cudaGetSymbolAddress((void**)&psc2, g_sc2);
    cudaGetSymbolAddress((void**)&psh2, g_sh2);

    const int SMEM = 768*4 + 2 * BUF_WRD * 4;    // 39936 B
    cudaFuncSetAttribute(gemm_mma<C2V, false, false>,
                         cudaFuncAttributeMaxDynamicSharedMemorySize, SMEM);
    cudaFuncSetAttribute(gemm_mma<C1V, false, true>,
                         cudaFuncAttributeMaxDynamicSharedMemorySize, SMEM);
    cudaFuncSetAttribute(gemm_mma<K2V, true, false>,
                         cudaFuncAttributeMaxDynamicSharedMemorySize, SMEM);

    // 1) 3-NN weights
    nn3_kernel<<<dim3(NPTS/256, BATCH), 256>>>(xyz1, xyz2);
    // 2) Z = P2 @ W1b^T   (16384 x 256, K=256; W1b = w1[:,128:384], ldw=384)
    gemm_mma<C2V, false, false><<<dim3(N1V/128, (BATCH*SPTS)/128), 256, SMEM>>>(
        points2, C2V, w1 + C1V, K1V, nullptr, nullptr, nullptr, nullptr,
        pZ, nullptr, nullptr, N1V);
    // 3) ZI = interp(Z)  (Z is L2-resident)
    interpZ_kernel<<<MROWS/8, 256>>>(pZ, pZI);
    // 4) Y1 = P1 @ W1a^T + ZI + b1  (K=128; W1a = w1[:,0:128], ldw=384)
    gemm_mma<C1V, false, true><<<dim3(N1V/128, MROWS/128), 256, SMEM>>>(
        points1, C1V, w1, K1V, b1, nullptr, nullptr, pZI,
        pY1, pps1, ppq1, N1V);
    bn_stats2<<<N1V, 128>>>(pps1, ppq1, g1, beta1, psc1, psh1);
    // 5) Y2 = relu(BN1(Y1)) @ W2^T + b2
    gemm_mma<K2V, true, false><<<dim3(N2V/128, MROWS/128), 256, SMEM>>>(
        pY1, K2V, w2, K2V, b2, psc1, psh1, nullptr,
        pY2, pps2, ppq2, N2V);
    bn_stats2<<<N2V, 128>>>(pps2, ppq2, g2, beta2, psc2, psh2);
    // 6) out = relu(BN2(Y2))
    bn_relu_out_kernel<<<(MROWS * N2V / 4) / 256, 256>>>(pY2, out);
}

// round 15
// speedup vs baseline: 1.3311x; 1.0070x over previous
#include <cuda_runtime.h>
#include <cuda_fp16.h>
#include <math.h>
#include <stdint.h>

// Problem constants
#define BATCH 8
#define NPTS  8192
#define SPTS  2048
#define C1V   128
#define C2V   256
#define MROWS 65536
#define K1V   384
#define N1V   256
#define K2V   256
#define N2V   128
#define RPARTS 512            // one partial per 128-row GEMM tile

// Scratch (device globals: allocation-free)
__device__ float g_Z [(size_t)BATCH * SPTS * N1V];   // P2 @ W1b^T  (16 MB, L2-resident)
__device__ float g_Y1[(size_t)MROWS * N1V];
__device__ float g_Y2[(size_t)MROWS * N2V];
__device__ int   g_idx[MROWS * 3];
__device__ float g_wt [MROWS * 3];
__device__ float g_ps1[N1V * RPARTS], g_pq1[N1V * RPARTS];   // [col][rowtile]
__device__ float g_ps2[N2V * RPARTS], g_pq2[N2V * RPARTS];
__device__ float g_sc1[N1V], g_sh1[N1V];
__device__ float g_sc2[N2V], g_sh2[N2V];

// ---------------------------------------------------------------------------
// fp16 / mma helpers
// ---------------------------------------------------------------------------
__device__ __forceinline__ uint32_t smem_u32(const void* p) {
    uint32_t a;
    asm("{ .reg .u64 t; cvta.to.shared.u64 t, %1; cvt.u32.u64 %0, t; }"
        : "=r"(a) : "l"(p));
    return a;
}
// a = ah + al in fp16 (captures ~22 mantissa bits of a)
__device__ __forceinline__ void split_pack_fp16(float e, float o,
                                                uint32_t& h, uint32_t& l) {
    __half he = __float2half_rn(e);
    __half ho = __float2half_rn(o);
    float re = e - __half2float(he);
    float ro = o - __half2float(ho);
    __half2 hp = __halves2half2(he, ho);
    __half2 lp = __floats2half2_rn(re, ro);
    h = *(uint32_t*)&hp;
    l = *(uint32_t*)&lp;
}
__device__ __forceinline__ uint32_t pack_fp16(float e, float o) {
    __half2 p = __floats2half2_rn(e, o);
    return *(uint32_t*)&p;
}
__device__ __forceinline__ void mma16(float* c, const uint32_t* a,
                                      uint32_t b0, uint32_t b1) {
    asm volatile(
        "mma.sync.aligned.m16n8k16.row.col.f32.f16.f16.f32 "
        "{%0,%1,%2,%3}, {%4,%5,%6,%7}, {%8,%9}, {%0,%1,%2,%3};"
        : "+f"(c[0]), "+f"(c[1]), "+f"(c[2]), "+f"(c[3])
        : "r"(a[0]), "r"(a[1]), "r"(a[2]), "r"(a[3]), "r"(b0), "r"(b1));
}
__device__ __forceinline__ void ldsm_x4(uint32_t* r, uint32_t addr) {
    asm volatile(
        "ldmatrix.sync.aligned.m8n8.x4.shared.b16 {%0,%1,%2,%3}, [%4];"
        : "=r"(r[0]), "=r"(r[1]), "=r"(r[2]), "=r"(r[3]) : "r"(addr));
}

// ---------------------------------------------------------------------------
// Kernel 1: 3-NN + interpolation weights (3-FMA inner loop)
// ---------------------------------------------------------------------------
__global__ void nn3_kernel(const float* __restrict__ xyz1,
                           const float* __restrict__ xyz2)
{
    __shared__ float4 s2[SPTS];
    const int b = blockIdx.y;
    const float* x2 = xyz2 + (size_t)b * SPTS * 3;
    for (int i = threadIdx.x; i < SPTS; i += blockDim.x) {
        float x = x2[i*3+0], y = x2[i*3+1], z = x2[i*3+2];
        s2[i] = make_float4(x, y, z, 0.5f*(x*x + y*y + z*z));
    }
    __syncthreads();

    const int n = blockIdx.x * blockDim.x + threadIdx.x;
    const int p = b * NPTS + n;
    const float ax = xyz1[(size_t)p*3+0];
    const float ay = xyz1[(size_t)p*3+1];
    const float az = xyz1[(size_t)p*3+2];
    const float an = ax*ax + ay*ay + az*az;

    float e0 = 1e30f, e1 = 1e30f, e2 = 1e30f;
    int   j0 = 0,     j1 = 0,     j2 = 0;
    #pragma unroll 8
    for (int s = 0; s < SPTS; s++) {
        float4 q = s2[s];
        float ee = fmaf(-ax, q.x, fmaf(-ay, q.y, fmaf(-az, q.z, q.w)));
        if (ee < e2) {
            if (ee < e1) {
                if (ee < e0) { e2=e1; j2=j1; e1=e0; j1=j0; e0=ee; j0=s; }
                else         { e2=e1; j2=j1; e1=ee; j1=s; }
            } else           { e2=ee; j2=s; }
        }
    }
    float d0 = sqrtf(fmaxf(fmaf(2.0f, e0, an), 0.0f));
    float d1 = sqrtf(fmaxf(fmaf(2.0f, e1, an), 0.0f));
    float d2 = sqrtf(fmaxf(fmaf(2.0f, e2, an), 0.0f));
    float r0 = 1.0f / (d0 + 1e-8f);
    float r1 = 1.0f / (d1 + 1e-8f);
    float r2 = 1.0f / (d2 + 1e-8f);
    float inv = 1.0f / (r0 + r1 + r2);
    g_wt[p*3+0] = r0*inv; g_wt[p*3+1] = r1*inv; g_wt[p*3+2] = r2*inv;
    g_idx[p*3+0] = j0;    g_idx[p*3+1] = j1;    g_idx[p*3+2] = j2;
}

// ---------------------------------------------------------------------------
// fp16x2 m16n8k16 GEMM (R14 pipeline) with row strides + FUSED INTERP:
//   Y[M,N] = op(A)[M,K] @ W[N,K]^T (+ bias) (+ interp_rows(Zsrc))
// y = (ah + al) * bh. CTA 128x128, BK=16, 8 warps, warp tile 32x64,
// double-buffered, 2 CTAs/SM, LDSM loads, term-major HMMA passes.
// FUSE_INTERP: epilogue gathers 3 rows of Zsrc (L2-resident) per output row
// using g_idx/g_wt and adds w0*z0+w1*z1+w2*z2 — identical math to the old
// interpZ kernel, but the 64MB ZI DRAM round-trip is gone.
// psum==nullptr skips the fused BN-stats epilogue (Z GEMM).
// TRANS_A fuses relu(a*scale+shift) (previous BN) into the A global load.
// ---------------------------------------------------------------------------
#define TROW_W 12                      // uint32 words per tile row
#define TILE_WRD (128 * TROW_W)
#define BUF_WRD (3 * TILE_WRD)         // Ah|Al|Bh per buffer

template<int KDIM, bool TRANS_A, bool FUSE_INTERP>
__global__ void __launch_bounds__(256, 2)
gemm_mma(const float* __restrict__ A, int lda,
         const float* __restrict__ W, int ldw,
         const float* __restrict__ bias,
         const float* __restrict__ aScale,
         const float* __restrict__ aShift,
         const float* __restrict__ Zsrc,
         float* __restrict__ Y,
         float* __restrict__ psum,
         float* __restrict__ psq,
         int N)
{
    extern __shared__ float sm[];
    float* sSc = sm;                    // [KDIM]
    float* sSh = sm + 384;              // [KDIM]
    uint32_t* tiles = (uint32_t*)(sm + 768);

    const int tid  = threadIdx.x;
    const int wid  = tid >> 5;
    const int lane = tid & 31;
    const int lg   = lane >> 2;
    const int lt   = lane & 3;
    const int wm   = (wid & 3) * 32;
    const int wn   = (wid >> 2) * 64;

    // ldmatrix per-lane addressing (bytes)
    const uint32_t tilesAddr = smem_u32(tiles);
    const int aRow = lane & 15;
    const int aOff = (lane >> 4) * 16;
    const int bRow = (lane & 7) + ((lane >> 4) << 3);
    const int bOff = ((lane >> 3) & 1) * 16;

    if (TRANS_A) {
        for (int i = tid; i < KDIM; i += 256) { sSc[i] = aScale[i]; sSh[i] = aShift[i]; }
        __syncthreads();
    }

    float acc[2][8][4];
    #pragma unroll
    for (int mt = 0; mt < 2; mt++)
        #pragma unroll
        for (int nt = 0; nt < 8; nt++)
            #pragma unroll
            for (int j = 0; j < 4; j++) acc[mt][nt][j] = 0.0f;

    const float* Ab = A + (size_t)blockIdx.y * 128 * lda;
    const float* Wb = W + (size_t)blockIdx.x * 128 * ldw;

    const int r = tid >> 2;            // 0..63
    const int q = tid & 3;             // float4 slot within k16

    float4 av[2], wv[2];
    auto g_load = [&](int k0) {
        #pragma unroll
        for (int i = 0; i < 2; i++) {
            int rr = i*64 + r;
            float4 v = *(const float4*)(Ab + (size_t)rr*lda + k0 + q*4);
            if (TRANS_A) {
                int kb = k0 + q*4;
                v.x = fmaxf(fmaf(v.x, sSc[kb+0], sSh[kb+0]), 0.0f);
                v.y = fmaxf(fmaf(v.y, sSc[kb+1], sSh[kb+1]), 0.0f);
                v.z = fmaxf(fmaf(v.z, sSc[kb+2], sSh[kb+2]), 0.0f);
                v.w = fmaxf(fmaf(v.w, sSc[kb+3], sSh[kb+3]), 0.0f);
            }
            av[i] = v;
            wv[i] = *(const float4*)(Wb + (size_t)rr*ldw + k0 + q*4);
        }
    };
    auto s_store = [&](int buf) {
        uint32_t* base = tiles + buf * BUF_WRD;
        #pragma unroll
        for (int i = 0; i < 2; i++) {
            const int rr = i*64 + r;
            const int wo = rr * TROW_W + q*2;
            uint32_t h0, l0, h1, l1;
            split_pack_fp16(av[i].x, av[i].y, h0, l0);
            split_pack_fp16(av[i].z, av[i].w, h1, l1);
            *(uint2*)(base + wo)              = make_uint2(h0, h1);  // Ah
            *(uint2*)(base + TILE_WRD + wo)   = make_uint2(l0, l1);  // Al
            const uint32_t bh0 = pack_fp16(wv[i].x, wv[i].y);
            const uint32_t bh1 = pack_fp16(wv[i].z, wv[i].w);
            *(uint2*)(base + 2*TILE_WRD + wo) = make_uint2(bh0, bh1); // Bh
        }
    };
    auto do_mma = [&](int buf) {
        const uint32_t tb = tilesAddr + buf * (BUF_WRD * 4);
        uint32_t ahr[2][4], alr[2][4];
        #pragma unroll
        for (int mt = 0; mt < 2; mt++) {
            const uint32_t ad = tb + (uint32_t)((wm + mt*16 + aRow) * TROW_W) * 4 + aOff;
            ldsm_x4(ahr[mt], ad);
            ldsm_x4(alr[mt], ad + TILE_WRD * 4);
        }
        #pragma unroll
        for (int half = 0; half < 2; half++) {
            uint32_t bh[2][4];
            #pragma unroll
            for (int g = 0; g < 2; g++) {
                const int ntp = half*2 + g;
                const uint32_t bd = tb + 2*TILE_WRD*4
                    + (uint32_t)((wn + ntp*16 + bRow) * TROW_W) * 4 + bOff;
                ldsm_x4(bh[g], bd);
            }
            #pragma unroll
            for (int g = 0; g < 2; g++)
                #pragma unroll
                for (int s = 0; s < 2; s++)
                    #pragma unroll
                    for (int mt = 0; mt < 2; mt++)
                        mma16(acc[mt][half*4 + g*2 + s], ahr[mt],
                              bh[g][2*s], bh[g][2*s+1]);
            #pragma unroll
            for (int g = 0; g < 2; g++)
                #pragma unroll
                for (int s = 0; s < 2; s++)
                    #pragma unroll
                    for (int mt = 0; mt < 2; mt++)
                        mma16(acc[mt][half*4 + g*2 + s], alr[mt],
                              bh[g][2*s], bh[g][2*s+1]);
        }
    };

    const int KT = KDIM / 16;
    g_load(0);
    s_store(0);
    __syncthreads();
    for (int kt = 0; kt < KT; kt++) {
        if (kt + 1 < KT) g_load((kt + 1) * 16);
        do_mma(kt & 1);
        if (kt + 1 < KT) {
            s_store((kt + 1) & 1);
            __syncthreads();
        }
    }

    // ---- Fused interp: acc += w0*Z[i0] + w1*Z[i1] + w2*Z[i2] (L2 gathers)
    if (FUSE_INTERP) {
        #pragma unroll
        for (int mt = 0; mt < 2; mt++) {
            #pragma unroll
            for (int rh = 0; rh < 2; rh++) {
                const int row = blockIdx.y*128 + wm + mt*16 + rh*8 + lg;
                const int b = row >> 13;
                const int i0 = g_idx[row*3+0];
                const int i1 = g_idx[row*3+1];
                const int i2 = g_idx[row*3+2];
                const float w0 = g_wt[row*3+0];
                const float w1 = g_wt[row*3+1];
                const float w2 = g_wt[row*3+2];
                const float* z0 = Zsrc + ((size_t)b*SPTS + i0) * N;
                const float* z1 = Zsrc + ((size_t)b*SPTS + i1) * N;
                const float* z2 = Zsrc + ((size_t)b*SPTS + i2) * N;
                #pragma unroll
                for (int nt = 0; nt < 8; nt++) {
                    const int col = blockIdx.x*128 + wn + nt*8 + 2*lt;
                    const float2 va = *(const float2*)(z0 + col);
                    const float2 vb = *(const float2*)(z1 + col);
                    const float2 vc = *(const float2*)(z2 + col);
                    acc[mt][nt][rh*2+0] += w0*va.x + w1*vb.x + w2*vc.x;
                    acc[mt][nt][rh*2+1] += w0*va.y + w1*vb.y + w2*vc.y;
                }
            }
        }
    }

    // ---- Epilogue: (+bias), store Y, optional fused BN partials
    #pragma unroll
    for (int nt = 0; nt < 8; nt++) {
        const int col = blockIdx.x*128 + wn + nt*8 + 2*lt;
        const float b0 = bias ? __ldg(&bias[col])   : 0.0f;
        const float b1 = bias ? __ldg(&bias[col+1]) : 0.0f;
        #pragma unroll
        for (int mt = 0; mt < 2; mt++) {
            const int row0 = blockIdx.y*128 + wm + mt*16 + lg;
            acc[mt][nt][0] += b0; acc[mt][nt][1] += b1;
            acc[mt][nt][2] += b0; acc[mt][nt][3] += b1;
            *(float2*)(Y + (size_t)row0 * N + col) =
                make_float2(acc[mt][nt][0], acc[mt][nt][1]);
            *(float2*)(Y + (size_t)(row0+8) * N + col) =
                make_float2(acc[mt][nt][2], acc[mt][nt][3]);
        }
    }

    if (psum != nullptr) {                // uniform branch
        __syncthreads();                  // reuse tiles as reduction space
        float* srs = (float*)tiles;
        float* srq = (float*)tiles + 512;
        #pragma unroll
        for (int nt = 0; nt < 8; nt++) {
            float sA = acc[0][nt][0] + acc[0][nt][2] + acc[1][nt][0] + acc[1][nt][2];
            float sB = acc[0][nt][1] + acc[0][nt][3] + acc[1][nt][1] + acc[1][nt][3];
            float qA = acc[0][nt][0]*acc[0][nt][0] + acc[0][nt][2]*acc[0][nt][2]
                     + acc[1][nt][0]*acc[1][nt][0] + acc[1][nt][2]*acc[1][nt][2];
            float qB = acc[0][nt][1]*acc[0][nt][1] + acc[0][nt][3]*acc[0][nt][3]
                     + acc[1][nt][1]*acc[1][nt][1] + acc[1][nt][3]*acc[1][nt][3];
            #pragma unroll
            for (int o = 4; o <= 16; o <<= 1) {
                sA += __shfl_xor_sync(0xFFFFFFFFu, sA, o);
                sB += __shfl_xor_sync(0xFFFFFFFFu, sB, o);
                qA += __shfl_xor_sync(0xFFFFFFFFu, qA, o);
                qB += __shfl_xor_sync(0xFFFFFFFFu, qB, o);
            }
            if (lane < 4) {
                srs[wid*64 + nt*8 + lane*2 + 0] = sA;
                srs[wid*64 + nt*8 + lane*2 + 1] = sB;
                srq[wid*64 + nt*8 + lane*2 + 0] = qA;
                srq[wid*64 + nt*8 + lane*2 + 1] = qB;
            }
        }
        __syncthreads();
        if (tid < 128) {
            const int w0 = tid >> 6, cc = tid & 63;
            float s = 0.0f, qq = 0.0f;
            #pragma unroll
            for (int k = 0; k < 4; k++) {
                s  += srs[(w0*4 + k)*64 + cc];
                qq += srq[(w0*4 + k)*64 + cc];
            }
            // transposed: [col][rowtile] -> contiguous per-channel reduction
            const size_t o = (size_t)(blockIdx.x*128 + tid) * RPARTS + blockIdx.y;
            psum[o] = s;
            psq [o] = qq;
        }
    }
}

// ---------------------------------------------------------------------------
// BN stats stage 2: one block per channel; 512 contiguous partials.
// ---------------------------------------------------------------------------
__global__ void bn_stats2(const float* __restrict__ ps, const float* __restrict__ pq,
                          const float* __restrict__ g,
                          const float* __restrict__ beta,
                          float* __restrict__ scale, float* __restrict__ shift)
{
    __shared__ float ss[4], sq[4];
    const int c = blockIdx.x, tid = threadIdx.x;   // 128 threads
    float4 v = ((const float4*)(ps + (size_t)c * RPARTS))[tid];
    float4 w = ((const float4*)(pq + (size_t)c * RPARTS))[tid];
    float s = (v.x + v.y) + (v.z + v.w);
    float q = (w.x + w.y) + (w.z + w.w);
    #pragma unroll
    for (int o = 16; o >= 1; o >>= 1) {
        s += __shfl_down_sync(0xFFFFFFFFu, s, o);
        q += __shfl_down_sync(0xFFFFFFFFu, q, o);
    }
    if ((tid & 31) == 0) { ss[tid >> 5] = s; sq[tid >> 5] = q; }
    __syncthreads();
    if (tid == 0) {
        double S = ((double)ss[0] + (double)ss[1]) + ((double)ss[2] + (double)ss[3]);
        double Q = ((double)sq[0] + (double)sq[1]) + ((double)sq[2] + (double)sq[3]);
        double mu  = S / (double)MROWS;
        double var = Q / (double)MROWS - mu * mu;
        float sc = g[c] / sqrtf((float)var + 1e-5f);
        scale[c] = sc;
        shift[c] = beta[c] - (float)mu * sc;
    }
}

// ---------------------------------------------------------------------------
// Final: out = relu(Y2 * scale2 + shift2)
// ---------------------------------------------------------------------------
__global__ void bn_relu_out_kernel(const float* __restrict__ Y,
                                   float* __restrict__ out)
{
    int i = blockIdx.x * blockDim.x + threadIdx.x;
    const float4 v = ((const float4*)Y)[i];
    int c = (i * 4) & (N2V - 1);
    float4 o;
    o.x = fmaxf(fmaf(v.x, g_sc2[c+0], g_sh2[c+0]), 0.0f);
    o.y = fmaxf(fmaf(v.y, g_sc2[c+1], g_sh2[c+1]), 0.0f);
    o.z = fmaxf(fmaf(v.z, g_sc2[c+2], g_sh2[c+2]), 0.0f);
    o.w = fmaxf(fmaf(v.w, g_sc2[c+3], g_sh2[c+3]), 0.0f);
    ((float4*)out)[i] = o;
}

// ---------------------------------------------------------------------------
// Launcher (graph-capturable)
// ---------------------------------------------------------------------------
extern "C" void kernel_launch(void* const* d_in, const int* in_sizes, int n_in,
                              void* d_out, int out_size)
{
    const float* xyz1    = (const float*)d_in[0];
    const float* xyz2    = (const float*)d_in[1];
    const float* points1 = (const float*)d_in[2];
    const float* points2 = (const float*)d_in[3];
    const float* w1      = (const float*)d_in[4];
    const float* b1      = (const float*)d_in[5];
    const float* g1      = (const float*)d_in[6];
    const float* beta1   = (const float*)d_in[7];
    const float* w2      = (const float*)d_in[8];
    const float* b2      = (const float*)d_in[9];
    const float* g2      = (const float*)d_in[10];
    const float* beta2   = (const float*)d_in[11];
    float* out = (float*)d_out;

    float *pZ, *pY1, *pY2, *pps1, *ppq1, *pps2, *ppq2, *psc1, *psh1, *psc2, *psh2;
    cudaGetSymbolAddress((void**)&pZ,   g_Z);
    cudaGetSymbolAddress((void**)&pY1,  g_Y1);
    cudaGetSymbolAddress((void**)&pY2,  g_Y2);
    cudaGetSymbolAddress((void**)&pps1, g_ps1);
    cudaGetSymbolAddress((void**)&ppq1, g_pq1);
    cudaGetSymbolAddress((void**)&pps2, g_ps2);
    cudaGetSymbolAddress((void**)&ppq2, g_pq2);
    cudaGetSymbolAddress((void**)&psc1, g_sc1);
    cudaGetSymbolAddress((void**)&psh1, g_sh1);
    cudaGetSymbolAddress((void**)&psc2, g_sc2);
    cudaGetSymbolAddress((void**)&psh2, g_sh2);

    const int SMEM = 768*4 + 2 * BUF_WRD * 4;    // 39936 B
    cudaFuncSetAttribute(gemm_mma<C2V, false, false>,
                         cudaFuncAttributeMaxDynamicSharedMemorySize, SMEM);
    cudaFuncSetAttribute(gemm_mma<C1V, false, true>,
                         cudaFuncAttributeMaxDynamicSharedMemorySize, SMEM);
    cudaFuncSetAttribute(gemm_mma<K2V, true, false>,
                         cudaFuncAttributeMaxDynamicSharedMemorySize, SMEM);

    // 1) 3-NN weights
    nn3_kernel<<<dim3(NPTS/256, BATCH), 256>>>(xyz1, xyz2);
    // 2) Z = P2 @ W1b^T   (16384 x 256, K=256; W1b = w1[:,128:384], ldw=384)
    gemm_mma<C2V, false, false><<<dim3(N1V/128, (BATCH*SPTS)/128), 256, SMEM>>>(
        points2, C2V, w1 + C1V, K1V, nullptr, nullptr, nullptr, nullptr,
        pZ, nullptr, nullptr, N1V);
    // 3) Y1 = P1 @ W1a^T + interp(Z) + b1  (K=128; interp fused in epilogue)
    gemm_mma<C1V, false, true><<<dim3(N1V/128, MROWS/128), 256, SMEM>>>(
        points1, C1V, w1, K1V, b1, nullptr, nullptr, pZ,
        pY1, pps1, ppq1, N1V);
    bn_stats2<<<N1V, 128>>>(pps1, ppq1, g1, beta1, psc1, psh1);
    // 4) Y2 = relu(BN1(Y1)) @ W2^T + b2
    gemm_mma<K2V, true, false><<<dim3(N2V/128, MROWS/128), 256, SMEM>>>(
        pY1, K2V, w2, K2V, b2, psc1, psh1, nullptr,
        pY2, pps2, ppq2, N2V);
    bn_stats2<<<N2V, 128>>>(pps2, ppq2, g2, beta2, psc2, psh2);
    // 5) out = relu(BN2(Y2))
    bn_relu_out_kernel<<<(MROWS * N2V / 4) / 256, 256>>>(pY2, out);
}